// round 5
// baseline (speedup 1.0000x reference)
#include <cuda_runtime.h>
#include <cuda_bf16.h>
#include <cstdint>

#define B_ 16
#define L_ 2048
#define D_ 64
#define NE (B_*L_*D_)
#define SST 72                      // smem row stride in bf16 elems (64+8)
#define CE 0.18033688011112042f     // (1/8)*log2(e)

// device scratch (no allocation)
__device__ __nv_bfloat16 g_Qh[NE], g_Ql[NE];
__device__ __nv_bfloat16 g_Kh[NE], g_Kl[NE];
__device__ __nv_bfloat16 g_VhT[NE], g_VlT[NE];        // [b][d][k]
__device__ unsigned char g_mask8[(size_t)B_*L_*L_];   // packed mask bytes (written by stats)
__device__ float g_I[B_*L_];                          // per-row 1/denom

// ---------------------------------------------------------------- helpers
__device__ __forceinline__ uint32_t smem_u32(const void* p) {
    return (uint32_t)__cvta_generic_to_shared(p);
}
__device__ __forceinline__ void cp16(uint32_t dst, const void* src) {
    asm volatile("cp.async.cg.shared.global [%0], [%1], 16;" :: "r"(dst), "l"(src));
}
__device__ __forceinline__ void cp_commit() { asm volatile("cp.async.commit_group;"); }
__device__ __forceinline__ void cp_wait0()  { asm volatile("cp.async.wait_group 0;"); }

__device__ __forceinline__ void ldsm_x4(uint32_t& r0, uint32_t& r1, uint32_t& r2, uint32_t& r3,
                                        uint32_t addr) {
    asm volatile("ldmatrix.sync.aligned.m8n8.x4.shared.b16 {%0,%1,%2,%3}, [%4];"
                 : "=r"(r0), "=r"(r1), "=r"(r2), "=r"(r3) : "r"(addr));
}
__device__ __forceinline__ void mma_bf16(float* c,
                                         uint32_t a0, uint32_t a1, uint32_t a2, uint32_t a3,
                                         uint32_t b0, uint32_t b1) {
    asm volatile(
        "mma.sync.aligned.m16n8k16.row.col.f32.bf16.bf16.f32 "
        "{%0,%1,%2,%3}, {%4,%5,%6,%7}, {%8,%9}, {%0,%1,%2,%3};\n"
        : "+f"(c[0]), "+f"(c[1]), "+f"(c[2]), "+f"(c[3])
        : "r"(a0), "r"(a1), "r"(a2), "r"(a3), "r"(b0), "r"(b1));
}
__device__ __forceinline__ uint32_t pack_bf16(float lo, float hi) {
    uint32_t r;
    asm("cvt.rn.bf16x2.f32 %0, %1, %2;" : "=r"(r) : "f"(hi), "f"(lo));
    return r;
}

// ---------------------------------------------------------------- K0a: split Q/K
__global__ __launch_bounds__(256) void split_kernel(const float* __restrict__ src, int which, int n) {
    __nv_bfloat16 *hi, *lo;
    if (which == 0) { hi = g_Qh; lo = g_Ql; }
    else            { hi = g_Kh; lo = g_Kl; }
    int i = blockIdx.x * blockDim.x + threadIdx.x;
    if (i < n) {
        float x = src[i];
        __nv_bfloat16 h = __float2bfloat16(x);
        hi[i] = h;
        lo[i] = __float2bfloat16(x - __bfloat162float(h));
    }
}

// ---------------------------------------------------------------- K0b: V transpose+split -> [b][d][k]
__global__ __launch_bounds__(256) void vtrans_kernel(const float* __restrict__ v) {
    __shared__ float t[32][33];
    int b = blockIdx.z, d0 = blockIdx.y * 32, k0 = blockIdx.x * 32;
    int tx = threadIdx.x, ty = threadIdx.y;   // block (32,8)
    #pragma unroll
    for (int j = 0; j < 32; j += 8)
        t[ty + j][tx] = v[((size_t)b * L_ + k0 + ty + j) * D_ + d0 + tx];
    __syncthreads();
    #pragma unroll
    for (int j = 0; j < 32; j += 8) {
        float x = t[tx][ty + j];
        int d = d0 + ty + j;
        size_t o = ((size_t)b * D_ + d) * L_ + k0 + tx;
        __nv_bfloat16 h = __float2bfloat16(x);
        g_VhT[o] = h;
        g_VlT[o] = __float2bfloat16(x - __bfloat162float(h));
    }
}

// ---------------- K1: stats pass — scores GEMM + exp + mask(int32) + row sums
// Writes: g_I (tiny) + g_mask8 (byte mask for pass 2). No score spill.
// grid (L/64, B), block 256 (warps 2M x 4N over 64x64 tiles). Dyn smem 90112B.
// layout: QH 0, QL 9216, KH[2] 18432, KL[2] 36864, M32[2] 55296, RED 88064
__global__ __launch_bounds__(256) void stats_kernel(const int* __restrict__ mask) {
    extern __shared__ char smem[];
    const int QH = 0, QL = 9216, KH = 18432, KL = 36864, M32 = 55296, RED = 88064;
    int b = blockIdx.y, m0 = blockIdx.x * 64, tid = threadIdx.x;
    int warp = tid >> 5, lane = tid & 31, gid = lane >> 2, tig = lane & 3;
    int wm = warp & 1, wn = warp >> 1;
    uint32_t sm = smem_u32(smem);

    // persistent Q tile
    {
        size_t qoff = ((size_t)b * L_ + m0) * D_;
        #pragma unroll
        for (int it = 0; it < 2; it++) {
            int i = tid + it * 256, r = i >> 3, c = i & 7;
            cp16(sm + QH + r * 144 + c * 16, g_Qh + qoff + r * 64 + c * 8);
            cp16(sm + QL + r * 144 + c * 16, g_Ql + qoff + r * 64 + c * 8);
        }
    }
    const int* mbase = mask + ((size_t)b * L_ + m0) * L_;

    // prologue: tile 0 (K + int32 mask)
    {
        size_t koff = ((size_t)b * L_) * D_;
        #pragma unroll
        for (int it = 0; it < 2; it++) {
            int i = tid + it * 256, r = i >> 3, c = i & 7;
            cp16(sm + KH + r * 144 + c * 16, g_Kh + koff + r * 64 + c * 8);
            cp16(sm + KL + r * 144 + c * 16, g_Kl + koff + r * 64 + c * 8);
        }
        #pragma unroll
        for (int it = 0; it < 4; it++) {
            int i = tid + it * 256, r = i >> 4, c = i & 15;
            cp16(sm + M32 + r * 256 + c * 16, mbase + (size_t)r * L_ + c * 4);
        }
        cp_commit();
    }

    float rsa[4], rsu[4];
    #pragma unroll
    for (int q = 0; q < 4; q++) { rsa[q] = 0.f; rsu[q] = 0.f; }

    uint32_t aoff = 2u * ((wm*32 + (lane & 15)) * SST + (lane >> 4) * 8);
    uint32_t boff = 2u * ((wn*16 + ((lane >> 4) & 1) * 8 + (lane & 7)) * SST + ((lane >> 3) & 1) * 8);
    uint32_t aQh = sm + QH + aoff, aQl = sm + QL + aoff;

    for (int kt = 0; kt < 32; kt++) {
        int d = kt & 1, n0 = kt * 64;
        cp_wait0();
        __syncthreads();
        if (kt < 31) {
            int d2 = (kt + 1) & 1, n2 = (kt + 1) * 64;
            size_t koff = ((size_t)b * L_ + n2) * D_;
            #pragma unroll
            for (int it = 0; it < 2; it++) {
                int i = tid + it * 256, r = i >> 3, c = i & 7;
                cp16(sm + KH + d2 * 9216 + r * 144 + c * 16, g_Kh + koff + r * 64 + c * 8);
                cp16(sm + KL + d2 * 9216 + r * 144 + c * 16, g_Kl + koff + r * 64 + c * 8);
            }
            #pragma unroll
            for (int it = 0; it < 4; it++) {
                int i = tid + it * 256, r = i >> 4, c = i & 15;
                cp16(sm + M32 + d2 * 16384 + r * 256 + c * 16, mbase + (size_t)r * L_ + n2 + c * 4);
            }
            cp_commit();
        }

        float acc[2][2][4];
        #pragma unroll
        for (int m = 0; m < 2; m++)
            #pragma unroll
            for (int j = 0; j < 2; j++)
                #pragma unroll
                for (int x = 0; x < 4; x++) acc[m][j][x] = 0.f;

        uint32_t aKh = sm + KH + d * 9216 + boff, aKl = sm + KL + d * 9216 + boff;
        #pragma unroll
        for (int kk = 0; kk < 4; kk++) {
            uint32_t kb = kk * 32;
            uint32_t ah[2][4], al[2][4], bh[4], bl[4];
            ldsm_x4(ah[0][0], ah[0][1], ah[0][2], ah[0][3], aQh + kb);
            ldsm_x4(ah[1][0], ah[1][1], ah[1][2], ah[1][3], aQh + kb + 32*SST);
            ldsm_x4(bh[0], bh[1], bh[2], bh[3], aKh + kb);
            ldsm_x4(bl[0], bl[1], bl[2], bl[3], aKl + kb);
            ldsm_x4(al[0][0], al[0][1], al[0][2], al[0][3], aQl + kb);
            ldsm_x4(al[1][0], al[1][1], al[1][2], al[1][3], aQl + kb + 32*SST);
            #pragma unroll
            for (int m = 0; m < 2; m++) {
                mma_bf16(acc[m][0], ah[m][0], ah[m][1], ah[m][2], ah[m][3], bh[0], bh[1]);
                mma_bf16(acc[m][1], ah[m][0], ah[m][1], ah[m][2], ah[m][3], bh[2], bh[3]);
                mma_bf16(acc[m][0], ah[m][0], ah[m][1], ah[m][2], ah[m][3], bl[0], bl[1]);
                mma_bf16(acc[m][1], ah[m][0], ah[m][1], ah[m][2], ah[m][3], bl[2], bl[3]);
                mma_bf16(acc[m][0], al[m][0], al[m][1], al[m][2], al[m][3], bh[0], bh[1]);
                mma_bf16(acc[m][1], al[m][0], al[m][1], al[m][2], al[m][3], bh[2], bh[3]);
            }
        }

        // epilogue: exp, mask(int32), sums, write byte mask for pass 2
        const int* smk = (const int*)(smem + M32 + d * 16384);
        #pragma unroll
        for (int m = 0; m < 2; m++) {
            #pragma unroll
            for (int pair = 0; pair < 2; pair++) {
                int q  = m * 2 + pair;
                int rl = wm*32 + m*16 + pair*8 + gid;
                int c0 = wn*16 + tig*2, c1 = c0 + 8;
                float e0 = exp2f(acc[m][0][pair*2]   * CE);
                float e1 = exp2f(acc[m][0][pair*2+1] * CE);
                float e2 = exp2f(acc[m][1][pair*2]   * CE);
                float e3 = exp2f(acc[m][1][pair*2+1] * CE);
                int mk0 = smk[rl*64 + c0], mk1 = smk[rl*64 + c0 + 1];
                int mk2 = smk[rl*64 + c1], mk3 = smk[rl*64 + c1 + 1];
                rsa[q] += (e0 + e1) + (e2 + e3);
                rsu[q] += (mk0 ? 0.f : e0) + (mk1 ? 0.f : e1)
                        + (mk2 ? 0.f : e2) + (mk3 ? 0.f : e3);
                size_t ro = ((size_t)b * L_ + m0 + rl) * L_ + n0;
                *(unsigned short*)(g_mask8 + ro + c0) =
                    (unsigned short)((mk0 ? 1u : 0u) | ((mk1 ? 1u : 0u) << 8));
                *(unsigned short*)(g_mask8 + ro + c1) =
                    (unsigned short)((mk2 ? 1u : 0u) | ((mk3 ? 1u : 0u) << 8));
            }
        }
    }

    // reduce: tig lanes then wn warps
    float* sRed = (float*)(smem + RED);
    #pragma unroll
    for (int q = 0; q < 4; q++) {
        #pragma unroll
        for (int o = 1; o <= 2; o <<= 1) {
            rsa[q] += __shfl_xor_sync(0xffffffffu, rsa[q], o);
            rsu[q] += __shfl_xor_sync(0xffffffffu, rsu[q], o);
        }
        if (tig == 0) {
            int rl = wm*32 + (q >> 1)*16 + (q & 1)*8 + gid;
            sRed[(wn*64 + rl)*2]     = rsa[q];
            sRed[(wn*64 + rl)*2 + 1] = rsu[q];
        }
    }
    __syncthreads();
    if (tid < 64) {
        float sa = 0.f, su = 0.f;
        #pragma unroll
        for (int w = 0; w < 4; w++) {
            sa += sRed[(w*64 + tid)*2];
            su += sRed[(w*64 + tid)*2 + 1];
        }
        g_I[b * L_ + m0 + tid] = 1.f / (su + 1e-8f * sa);
    }
}

// ---------------- K2: main pass — scores GEMM (recompute) + attn write + fused AV
// grid (L/64, B), block 128 (4 warps, each: 16 q-rows x 64 keys). Dyn smem 100608B.
// layout: QH 0, QL 9216, KH[2] 18432, KL[2] 36864, VH[2] 55296, VL[2] 73728,
//         MB[2] 92160, II 100352
__global__ __launch_bounds__(128) void main_kernel(float* __restrict__ attn,
                                                   float* __restrict__ out) {
    extern __shared__ char smem[];
    const int QH = 0, QL = 9216, KH = 18432, KL = 36864, VH = 55296, VL = 73728,
              MB = 92160, II = 100352;
    int b = blockIdx.y, m0 = blockIdx.x * 64, tid = threadIdx.x;
    int warp = tid >> 5, lane = tid & 31, gid = lane >> 2, tig = lane & 3;
    uint32_t sm = smem_u32(smem);

    float* sI = (float*)(smem + II);
    if (tid < 64) sI[tid] = g_I[b * L_ + m0 + tid];

    // persistent Q tile (64 rows)
    {
        size_t qoff = ((size_t)b * L_ + m0) * D_;
        #pragma unroll
        for (int it = 0; it < 4; it++) {
            int i = tid + it * 128, r = i >> 3, c = i & 7;
            cp16(sm + QH + r * 144 + c * 16, g_Qh + qoff + r * 64 + c * 8);
            cp16(sm + QL + r * 144 + c * 16, g_Ql + qoff + r * 64 + c * 8);
        }
    }
    const unsigned char* mbase8 = g_mask8 + ((size_t)b * L_ + m0) * L_;

    // prologue: tile 0 (K, V, byte mask)
    {
        size_t koff = ((size_t)b * L_) * D_;
        #pragma unroll
        for (int it = 0; it < 4; it++) {
            int i = tid + it * 128, r = i >> 3, c = i & 7;
            cp16(sm + KH + r * 144 + c * 16, g_Kh + koff + r * 64 + c * 8);
            cp16(sm + KL + r * 144 + c * 16, g_Kl + koff + r * 64 + c * 8);
            cp16(sm + VH + r * 144 + c * 16, g_VhT + ((size_t)b * D_ + r) * L_ + c * 8);
            cp16(sm + VL + r * 144 + c * 16, g_VlT + ((size_t)b * D_ + r) * L_ + c * 8);
        }
        #pragma unroll
        for (int it = 0; it < 2; it++) {
            int i = tid + it * 128, r = i >> 2, c = i & 3;
            cp16(sm + MB + r * 64 + c * 16, mbase8 + (size_t)r * L_ + c * 16);
        }
        cp_commit();
    }

    uint32_t aoff = 2u * ((warp*16 + (lane & 15)) * SST + (lane >> 4) * 8);
    uint32_t boffg[4];
    #pragma unroll
    for (int g = 0; g < 4; g++)
        boffg[g] = 2u * ((g*16 + ((lane >> 4) & 1) * 8 + (lane & 7)) * SST + ((lane >> 3) & 1) * 8);
    uint32_t aQh = sm + QH + aoff, aQl = sm + QL + aoff;

    int r0 = warp*16 + gid, r1 = r0 + 8;

    float accO[8][4];
    #pragma unroll
    for (int j = 0; j < 8; j++)
        #pragma unroll
        for (int x = 0; x < 4; x++) accO[j][x] = 0.f;

    for (int kt = 0; kt < 32; kt++) {
        int d = kt & 1, n0 = kt * 64;
        cp_wait0();
        __syncthreads();
        if (kt < 31) {
            int d2 = (kt + 1) & 1, n2 = (kt + 1) * 64;
            size_t koff = ((size_t)b * L_ + n2) * D_;
            #pragma unroll
            for (int it = 0; it < 4; it++) {
                int i = tid + it * 128, r = i >> 3, c = i & 7;
                cp16(sm + KH + d2*9216 + r * 144 + c * 16, g_Kh + koff + r * 64 + c * 8);
                cp16(sm + KL + d2*9216 + r * 144 + c * 16, g_Kl + koff + r * 64 + c * 8);
                cp16(sm + VH + d2*9216 + r * 144 + c * 16, g_VhT + ((size_t)b * D_ + r) * L_ + n2 + c * 8);
                cp16(sm + VL + d2*9216 + r * 144 + c * 16, g_VlT + ((size_t)b * D_ + r) * L_ + n2 + c * 8);
            }
            #pragma unroll
            for (int it = 0; it < 2; it++) {
                int i = tid + it * 128, r = i >> 2, c = i & 3;
                cp16(sm + MB + d2*4096 + r * 64 + c * 16, mbase8 + (size_t)r * L_ + n2 + c * 16);
            }
            cp_commit();
        }

        // ---- scores: S(16x64) = Q_warp · K^T  (3-product bf16 split)
        float accS[8][4];
        #pragma unroll
        for (int j = 0; j < 8; j++)
            #pragma unroll
            for (int x = 0; x < 4; x++) accS[j][x] = 0.f;

        uint32_t kh_base = sm + KH + d*9216, kl_base = sm + KL + d*9216;
        #pragma unroll
        for (int kk = 0; kk < 4; kk++) {
            uint32_t kb = kk * 32;
            uint32_t ah[4], al[4];
            ldsm_x4(ah[0], ah[1], ah[2], ah[3], aQh + kb);
            ldsm_x4(al[0], al[1], al[2], al[3], aQl + kb);
            #pragma unroll
            for (int g = 0; g < 4; g++) {
                uint32_t bh[4], bl[4];
                ldsm_x4(bh[0], bh[1], bh[2], bh[3], kh_base + boffg[g] + kb);
                ldsm_x4(bl[0], bl[1], bl[2], bl[3], kl_base + boffg[g] + kb);
                #pragma unroll
                for (int h = 0; h < 2; h++) {
                    int j = g*2 + h;
                    mma_bf16(accS[j], ah[0], ah[1], ah[2], ah[3], bh[h*2], bh[h*2+1]);
                    mma_bf16(accS[j], ah[0], ah[1], ah[2], ah[3], bl[h*2], bl[h*2+1]);
                    mma_bf16(accS[j], al[0], al[1], al[2], al[3], bh[h*2], bh[h*2+1]);
                }
            }
        }

        // ---- epilogue: exp, mask, *I, write attn, pack bf16 hi/lo A-fragments
        const unsigned char* smk = (const unsigned char*)(smem + MB + d*4096);
        float inv0 = sI[r0], inv1 = sI[r1];
        uint32_t u0[8], u1[8], l0[8], l1[8];
        #pragma unroll
        for (int j = 0; j < 8; j++) {
            int c = j*8 + tig*2;
            float e0 = exp2f(accS[j][0] * CE);
            float e1 = exp2f(accS[j][1] * CE);
            float e2 = exp2f(accS[j][2] * CE);
            float e3 = exp2f(accS[j][3] * CE);
            unsigned short mk0 = *(const unsigned short*)(smk + r0*64 + c);
            unsigned short mk1 = *(const unsigned short*)(smk + r1*64 + c);
            float a0 = (mk0 & 0xff) ? 0.f : e0 * inv0;
            float a1 = (mk0 >> 8)   ? 0.f : e1 * inv0;
            float a2 = (mk1 & 0xff) ? 0.f : e2 * inv1;
            float a3 = (mk1 >> 8)   ? 0.f : e3 * inv1;
            *(float2*)(attn + ((size_t)b * L_ + m0 + r0) * L_ + n0 + c) = make_float2(a0, a1);
            *(float2*)(attn + ((size_t)b * L_ + m0 + r1) * L_ + n0 + c) = make_float2(a2, a3);
            u0[j] = pack_bf16(a0, a1);
            u1[j] = pack_bf16(a2, a3);
            float h0 = __bfloat162float(__float2bfloat16(a0));
            float h1 = __bfloat162float(__float2bfloat16(a1));
            float h2 = __bfloat162float(__float2bfloat16(a2));
            float h3 = __bfloat162float(__float2bfloat16(a3));
            l0[j] = pack_bf16(a0 - h0, a1 - h1);
            l1[j] = pack_bf16(a2 - h2, a3 - h3);
        }

        // ---- AV: O(16x64) += P(16x64) · V(64k x 64d), P fragments in registers
        uint32_t vh_base = sm + VH + d*9216, vl_base = sm + VL + d*9216;
        #pragma unroll
        for (int kc = 0; kc < 4; kc++) {
            uint32_t kb = kc * 32;
            uint32_t pa0 = u0[2*kc], pa1 = u1[2*kc], pa2 = u0[2*kc+1], pa3 = u1[2*kc+1];
            uint32_t qa0 = l0[2*kc], qa1 = l1[2*kc], qa2 = l0[2*kc+1], qa3 = l1[2*kc+1];
            #pragma unroll
            for (int g = 0; g < 4; g++) {
                uint32_t vh[4], vl[4];
                ldsm_x4(vh[0], vh[1], vh[2], vh[3], vh_base + boffg[g] + kb);
                ldsm_x4(vl[0], vl[1], vl[2], vl[3], vl_base + boffg[g] + kb);
                #pragma unroll
                for (int h = 0; h < 2; h++) {
                    int j = g*2 + h;
                    mma_bf16(accO[j], pa0, pa1, pa2, pa3, vh[h*2], vh[h*2+1]);
                    mma_bf16(accO[j], pa0, pa1, pa2, pa3, vl[h*2], vl[h*2+1]);
                    mma_bf16(accO[j], qa0, qa1, qa2, qa3, vh[h*2], vh[h*2+1]);
                }
            }
        }
    }

    // ---- out epilogue
    #pragma unroll
    for (int j = 0; j < 8; j++) {
        int c = j*8 + tig*2;
        *(float2*)(out + ((size_t)b * L_ + m0 + r0) * D_ + c) = make_float2(accO[j][0], accO[j][1]);
        *(float2*)(out + ((size_t)b * L_ + m0 + r1) * D_ + c) = make_float2(accO[j][2], accO[j][3]);
    }
}

// ----------------------------------------------------------------- launcher
extern "C" void kernel_launch(void* const* d_in, const int* in_sizes, int n_in,
                              void* d_out, int out_size) {
    const float* q = (const float*)d_in[0];
    const float* k = (const float*)d_in[1];
    const float* v = (const float*)d_in[2];
    const int* mask = (const int*)d_in[3];
    float* out  = (float*)d_out;
    float* attn = out + (size_t)B_ * L_ * D_;

    cudaFuncSetAttribute(stats_kernel, cudaFuncAttributeMaxDynamicSharedMemorySize, 90112);
    cudaFuncSetAttribute(main_kernel,  cudaFuncAttributeMaxDynamicSharedMemorySize, 100608);

    int n = NE, nb = (n + 255) / 256;
    split_kernel<<<nb, 256>>>(q, 0, n);
    split_kernel<<<nb, 256>>>(k, 1, n);
    vtrans_kernel<<<dim3(L_/32, 2, B_), dim3(32, 8)>>>(v);

    stats_kernel<<<dim3(L_/64, B_), 256, 90112>>>(mask);
    main_kernel<<<dim3(L_/64, B_), 128, 100608>>>(attn, out);
}

// round 6
// speedup vs baseline: 1.1197x; 1.1197x over previous
#include <cuda_runtime.h>
#include <cuda_bf16.h>
#include <cstdint>

#define B_ 16
#define L_ 2048
#define D_ 64
#define NE (B_*L_*D_)
#define SST 72                      // smem row stride in bf16 elems (64+8)
#define CE 0.18033688011112042f     // (1/8)*log2(e)

// device scratch (no allocation)
__device__ __nv_bfloat16 g_Qh[NE], g_Ql[NE];
__device__ __nv_bfloat16 g_Kh[NE], g_Kl[NE];
__device__ __nv_bfloat16 g_VhT[NE], g_VlT[NE];        // [b][d][k]
__device__ float g_I[B_*L_];                          // per-row 1/denom

// ---------------------------------------------------------------- helpers
__device__ __forceinline__ uint32_t smem_u32(const void* p) {
    return (uint32_t)__cvta_generic_to_shared(p);
}
__device__ __forceinline__ void cp16(uint32_t dst, const void* src) {
    asm volatile("cp.async.cg.shared.global [%0], [%1], 16;" :: "r"(dst), "l"(src));
}
__device__ __forceinline__ void cp_commit() { asm volatile("cp.async.commit_group;"); }
__device__ __forceinline__ void cp_wait0()  { asm volatile("cp.async.wait_group 0;"); }

__device__ __forceinline__ void ldsm_x4(uint32_t& r0, uint32_t& r1, uint32_t& r2, uint32_t& r3,
                                        uint32_t addr) {
    asm volatile("ldmatrix.sync.aligned.m8n8.x4.shared.b16 {%0,%1,%2,%3}, [%4];"
                 : "=r"(r0), "=r"(r1), "=r"(r2), "=r"(r3) : "r"(addr));
}
__device__ __forceinline__ void mma_bf16(float* c,
                                         uint32_t a0, uint32_t a1, uint32_t a2, uint32_t a3,
                                         uint32_t b0, uint32_t b1) {
    asm volatile(
        "mma.sync.aligned.m16n8k16.row.col.f32.bf16.bf16.f32 "
        "{%0,%1,%2,%3}, {%4,%5,%6,%7}, {%8,%9}, {%0,%1,%2,%3};\n"
        : "+f"(c[0]), "+f"(c[1]), "+f"(c[2]), "+f"(c[3])
        : "r"(a0), "r"(a1), "r"(a2), "r"(a3), "r"(b0), "r"(b1));
}
__device__ __forceinline__ uint32_t pack_bf16(float lo, float hi) {
    uint32_t r;
    asm("cvt.rn.bf16x2.f32 %0, %1, %2;" : "=r"(r) : "f"(hi), "f"(lo));
    return r;
}

// ---------------------------------------------------------------- K0a: split Q/K
__global__ __launch_bounds__(256) void split_kernel(const float* __restrict__ src, int which, int n) {
    __nv_bfloat16 *hi, *lo;
    if (which == 0) { hi = g_Qh; lo = g_Ql; }
    else            { hi = g_Kh; lo = g_Kl; }
    int i = blockIdx.x * blockDim.x + threadIdx.x;
    if (i < n) {
        float x = src[i];
        __nv_bfloat16 h = __float2bfloat16(x);
        hi[i] = h;
        lo[i] = __float2bfloat16(x - __bfloat162float(h));
    }
}

// ---------------------------------------------------------------- K0b: V transpose+split -> [b][d][k]
__global__ __launch_bounds__(256) void vtrans_kernel(const float* __restrict__ v) {
    __shared__ float t[32][33];
    int b = blockIdx.z, d0 = blockIdx.y * 32, k0 = blockIdx.x * 32;
    int tx = threadIdx.x, ty = threadIdx.y;   // block (32,8)
    #pragma unroll
    for (int j = 0; j < 32; j += 8)
        t[ty + j][tx] = v[((size_t)b * L_ + k0 + ty + j) * D_ + d0 + tx];
    __syncthreads();
    #pragma unroll
    for (int j = 0; j < 32; j += 8) {
        float x = t[tx][ty + j];
        int d = d0 + ty + j;
        size_t o = ((size_t)b * D_ + d) * L_ + k0 + tx;
        __nv_bfloat16 h = __float2bfloat16(x);
        g_VhT[o] = h;
        g_VlT[o] = __float2bfloat16(x - __bfloat162float(h));
    }
}

// ---------------- K1: fully fused — scores GEMM + exp + mask + u-write + AV + I
// grid (L/64, B), block 128 (4 warps, each 16 q-rows x all 64 k-cols of a tile).
// Writes unscaled u = mask?0:exp(s) into attn region; O scaled by I at the end;
// g_I written for the rescale pass. Dyn smem 92160B.
// layout: QH 0, QL 9216, KH[2] 18432, KL[2] 36864, VH[2] 55296, VL[2] 73728
__global__ __launch_bounds__(128) void main_kernel(const int* __restrict__ mask,
                                                   float* __restrict__ attn,
                                                   float* __restrict__ out) {
    extern __shared__ char smem[];
    const int QH = 0, QL = 9216, KH = 18432, KL = 36864, VH = 55296, VL = 73728;
    int b = blockIdx.y, m0 = blockIdx.x * 64, tid = threadIdx.x;
    int warp = tid >> 5, lane = tid & 31, gid = lane >> 2, tig = lane & 3;
    uint32_t sm = smem_u32(smem);

    // persistent Q tile (64 rows)
    {
        size_t qoff = ((size_t)b * L_ + m0) * D_;
        #pragma unroll
        for (int it = 0; it < 4; it++) {
            int i = tid + it * 128, r = i >> 3, c = i & 7;
            cp16(sm + QH + r * 144 + c * 16, g_Qh + qoff + r * 64 + c * 8);
            cp16(sm + QL + r * 144 + c * 16, g_Ql + qoff + r * 64 + c * 8);
        }
    }

    // prologue: tile 0 (K, V)
    {
        size_t koff = ((size_t)b * L_) * D_;
        #pragma unroll
        for (int it = 0; it < 4; it++) {
            int i = tid + it * 128, r = i >> 3, c = i & 7;
            cp16(sm + KH + r * 144 + c * 16, g_Kh + koff + r * 64 + c * 8);
            cp16(sm + KL + r * 144 + c * 16, g_Kl + koff + r * 64 + c * 8);
            cp16(sm + VH + r * 144 + c * 16, g_VhT + ((size_t)b * D_ + r) * L_ + c * 8);
            cp16(sm + VL + r * 144 + c * 16, g_VlT + ((size_t)b * D_ + r) * L_ + c * 8);
        }
        cp_commit();
    }

    uint32_t aoff = 2u * ((warp*16 + (lane & 15)) * SST + (lane >> 4) * 8);
    uint32_t boffg[4];
    #pragma unroll
    for (int g = 0; g < 4; g++)
        boffg[g] = 2u * ((g*16 + ((lane >> 4) & 1) * 8 + (lane & 7)) * SST + ((lane >> 3) & 1) * 8);
    uint32_t aQh = sm + QH + aoff, aQl = sm + QL + aoff;

    int r0 = warp*16 + gid, r1 = r0 + 8;
    const int* mrow0 = mask + ((size_t)(b * L_ + m0 + r0)) * L_ + tig * 2;
    const int* mrow1 = mask + ((size_t)(b * L_ + m0 + r1)) * L_ + tig * 2;

    float accO[8][4];
    #pragma unroll
    for (int j = 0; j < 8; j++)
        #pragma unroll
        for (int x = 0; x < 4; x++) accO[j][x] = 0.f;

    float rsa0 = 0.f, rsa1 = 0.f, rsu0 = 0.f, rsu1 = 0.f;

    for (int kt = 0; kt < 32; kt++) {
        int d = kt & 1, n0 = kt * 64;
        cp_wait0();
        __syncthreads();

        // mask prefetch (registers) — latency covered by the scores GEMM below
        int2 mk0[8], mk1[8];
        #pragma unroll
        for (int j = 0; j < 8; j++) {
            mk0[j] = __ldg((const int2*)(mrow0 + n0 + j*8));
            mk1[j] = __ldg((const int2*)(mrow1 + n0 + j*8));
        }

        if (kt < 31) {
            int d2 = (kt + 1) & 1, n2 = (kt + 1) * 64;
            size_t koff = ((size_t)b * L_ + n2) * D_;
            #pragma unroll
            for (int it = 0; it < 4; it++) {
                int i = tid + it * 128, r = i >> 3, c = i & 7;
                cp16(sm + KH + d2*9216 + r * 144 + c * 16, g_Kh + koff + r * 64 + c * 8);
                cp16(sm + KL + d2*9216 + r * 144 + c * 16, g_Kl + koff + r * 64 + c * 8);
                cp16(sm + VH + d2*9216 + r * 144 + c * 16, g_VhT + ((size_t)b * D_ + r) * L_ + n2 + c * 8);
                cp16(sm + VL + d2*9216 + r * 144 + c * 16, g_VlT + ((size_t)b * D_ + r) * L_ + n2 + c * 8);
            }
            cp_commit();
        }

        // ---- scores: S(16x64) = Q_warp · K^T  (3-product bf16 split)
        float accS[8][4];
        #pragma unroll
        for (int j = 0; j < 8; j++)
            #pragma unroll
            for (int x = 0; x < 4; x++) accS[j][x] = 0.f;

        uint32_t kh_base = sm + KH + d*9216, kl_base = sm + KL + d*9216;
        #pragma unroll
        for (int kk = 0; kk < 4; kk++) {
            uint32_t kb = kk * 32;
            uint32_t ah[4], al[4];
            ldsm_x4(ah[0], ah[1], ah[2], ah[3], aQh + kb);
            ldsm_x4(al[0], al[1], al[2], al[3], aQl + kb);
            #pragma unroll
            for (int g = 0; g < 4; g++) {
                uint32_t bh[4], bl[4];
                ldsm_x4(bh[0], bh[1], bh[2], bh[3], kh_base + boffg[g] + kb);
                ldsm_x4(bl[0], bl[1], bl[2], bl[3], kl_base + boffg[g] + kb);
                #pragma unroll
                for (int h = 0; h < 2; h++) {
                    int j = g*2 + h;
                    mma_bf16(accS[j], ah[0], ah[1], ah[2], ah[3], bh[h*2], bh[h*2+1]);
                    mma_bf16(accS[j], ah[0], ah[1], ah[2], ah[3], bl[h*2], bl[h*2+1]);
                    mma_bf16(accS[j], al[0], al[1], al[2], al[3], bh[h*2], bh[h*2+1]);
                }
            }
        }

        // ---- epilogue: exp, mask, sums, write unscaled u, pack bf16 hi/lo
        uint32_t u0[8], u1[8], l0[8], l1[8];
        #pragma unroll
        for (int j = 0; j < 8; j++) {
            int c = j*8 + tig*2;
            float e0 = exp2f(accS[j][0] * CE);
            float e1 = exp2f(accS[j][1] * CE);
            float e2 = exp2f(accS[j][2] * CE);
            float e3 = exp2f(accS[j][3] * CE);
            rsa0 += e0 + e1;
            rsa1 += e2 + e3;
            float a0 = mk0[j].x ? 0.f : e0;
            float a1 = mk0[j].y ? 0.f : e1;
            float a2 = mk1[j].x ? 0.f : e2;
            float a3 = mk1[j].y ? 0.f : e3;
            rsu0 += a0 + a1;
            rsu1 += a2 + a3;
            *(float2*)(attn + ((size_t)b * L_ + m0 + r0) * L_ + n0 + c) = make_float2(a0, a1);
            *(float2*)(attn + ((size_t)b * L_ + m0 + r1) * L_ + n0 + c) = make_float2(a2, a3);
            u0[j] = pack_bf16(a0, a1);
            u1[j] = pack_bf16(a2, a3);
            float h0 = __bfloat162float(__float2bfloat16(a0));
            float h1 = __bfloat162float(__float2bfloat16(a1));
            float h2 = __bfloat162float(__float2bfloat16(a2));
            float h3 = __bfloat162float(__float2bfloat16(a3));
            l0[j] = pack_bf16(a0 - h0, a1 - h1);
            l1[j] = pack_bf16(a2 - h2, a3 - h3);
        }

        // ---- AV: O_u(16x64) += u(16x64) · V, fragments already in registers
        uint32_t vh_base = sm + VH + d*9216, vl_base = sm + VL + d*9216;
        #pragma unroll
        for (int kc = 0; kc < 4; kc++) {
            uint32_t kb = kc * 32;
            uint32_t pa0 = u0[2*kc], pa1 = u1[2*kc], pa2 = u0[2*kc+1], pa3 = u1[2*kc+1];
            uint32_t qa0 = l0[2*kc], qa1 = l1[2*kc], qa2 = l0[2*kc+1], qa3 = l1[2*kc+1];
            #pragma unroll
            for (int g = 0; g < 4; g++) {
                uint32_t vh[4], vl[4];
                ldsm_x4(vh[0], vh[1], vh[2], vh[3], vh_base + boffg[g] + kb);
                ldsm_x4(vl[0], vl[1], vl[2], vl[3], vl_base + boffg[g] + kb);
                #pragma unroll
                for (int h = 0; h < 2; h++) {
                    int j = g*2 + h;
                    mma_bf16(accO[j], pa0, pa1, pa2, pa3, vh[h*2], vh[h*2+1]);
                    mma_bf16(accO[j], pa0, pa1, pa2, pa3, vl[h*2], vl[h*2+1]);
                    mma_bf16(accO[j], qa0, qa1, qa2, qa3, vh[h*2], vh[h*2+1]);
                }
            }
        }
    }

    // ---- denominators: reduce over tig lanes (butterfly keeps all lanes valid)
    #pragma unroll
    for (int o = 1; o <= 2; o <<= 1) {
        rsa0 += __shfl_xor_sync(0xffffffffu, rsa0, o);
        rsa1 += __shfl_xor_sync(0xffffffffu, rsa1, o);
        rsu0 += __shfl_xor_sync(0xffffffffu, rsu0, o);
        rsu1 += __shfl_xor_sync(0xffffffffu, rsu1, o);
    }
    float I0 = 1.f / (rsu0 + 1e-8f * rsa0);
    float I1 = 1.f / (rsu1 + 1e-8f * rsa1);
    if (tig == 0) {
        g_I[b * L_ + m0 + r0] = I0;
        g_I[b * L_ + m0 + r1] = I1;
    }

    // ---- out epilogue: O = O_u * I
    #pragma unroll
    for (int j = 0; j < 8; j++) {
        int c = j*8 + tig*2;
        *(float2*)(out + ((size_t)b * L_ + m0 + r0) * D_ + c) =
            make_float2(accO[j][0] * I0, accO[j][1] * I0);
        *(float2*)(out + ((size_t)b * L_ + m0 + r1) * D_ + c) =
            make_float2(accO[j][2] * I1, accO[j][3] * I1);
    }
}

// ---------------- K2: rescale attn rows by I (streaming, one CTA per row)
__global__ __launch_bounds__(256) void rescale_kernel(float* __restrict__ attn) {
    int row = blockIdx.x;
    float inv = g_I[row];
    float4* p = (float4*)(attn + (size_t)row * L_);
    int tid = threadIdx.x;
    #pragma unroll
    for (int it = 0; it < 2; it++) {
        float4 v = p[tid + it * 256];
        v.x *= inv; v.y *= inv; v.z *= inv; v.w *= inv;
        p[tid + it * 256] = v;
    }
}

// ----------------------------------------------------------------- launcher
extern "C" void kernel_launch(void* const* d_in, const int* in_sizes, int n_in,
                              void* d_out, int out_size) {
    const float* q = (const float*)d_in[0];
    const float* k = (const float*)d_in[1];
    const float* v = (const float*)d_in[2];
    const int* mask = (const int*)d_in[3];
    float* out  = (float*)d_out;
    float* attn = out + (size_t)B_ * L_ * D_;

    cudaFuncSetAttribute(main_kernel, cudaFuncAttributeMaxDynamicSharedMemorySize, 92160);

    int n = NE, nb = (n + 255) / 256;
    split_kernel<<<nb, 256>>>(q, 0, n);
    split_kernel<<<nb, 256>>>(k, 1, n);
    vtrans_kernel<<<dim3(L_/32, 2, B_), dim3(32, 8)>>>(v);

    main_kernel<<<dim3(L_/64, B_), 128, 92160>>>(mask, attn, out);
    rescale_kernel<<<B_*L_, 256>>>(attn);
}

// round 7
// speedup vs baseline: 1.1811x; 1.0549x over previous
#include <cuda_runtime.h>
#include <cuda_bf16.h>
#include <cstdint>

#define B_ 16
#define L_ 2048
#define D_ 64
#define NE (B_*L_*D_)
#define CE 0.18033688011112042f     // (1/8)*log2(e)

// device scratch (no allocation)
__device__ __nv_bfloat16 g_Qh[NE], g_Ql[NE];
__device__ __nv_bfloat16 g_Kh[NE], g_Kl[NE];
__device__ __nv_bfloat16 g_VhT[NE], g_VlT[NE];        // [b][d][k]
__device__ float g_I[B_*L_];                          // per-row 1/denom

// ---------------------------------------------------------------- helpers
__device__ __forceinline__ uint32_t smem_u32(const void* p) {
    return (uint32_t)__cvta_generic_to_shared(p);
}
__device__ __forceinline__ void cp16(uint32_t dst, const void* src) {
    asm volatile("cp.async.cg.shared.global [%0], [%1], 16;" :: "r"(dst), "l"(src));
}
__device__ __forceinline__ void cp_commit() { asm volatile("cp.async.commit_group;"); }
__device__ __forceinline__ void cp_wait0()  { asm volatile("cp.async.wait_group 0;"); }
__device__ __forceinline__ void cp_wait1()  { asm volatile("cp.async.wait_group 1;"); }

__device__ __forceinline__ void ldsm_x4(uint32_t& r0, uint32_t& r1, uint32_t& r2, uint32_t& r3,
                                        uint32_t addr) {
    asm volatile("ldmatrix.sync.aligned.m8n8.x4.shared.b16 {%0,%1,%2,%3}, [%4];"
                 : "=r"(r0), "=r"(r1), "=r"(r2), "=r"(r3) : "r"(addr));
}
__device__ __forceinline__ void mma_bf16(float* c,
                                         uint32_t a0, uint32_t a1, uint32_t a2, uint32_t a3,
                                         uint32_t b0, uint32_t b1) {
    asm volatile(
        "mma.sync.aligned.m16n8k16.row.col.f32.bf16.bf16.f32 "
        "{%0,%1,%2,%3}, {%4,%5,%6,%7}, {%8,%9}, {%0,%1,%2,%3};\n"
        : "+f"(c[0]), "+f"(c[1]), "+f"(c[2]), "+f"(c[3])
        : "r"(a0), "r"(a1), "r"(a2), "r"(a3), "r"(b0), "r"(b1));
}
__device__ __forceinline__ uint32_t pack_bf16(float lo, float hi) {
    uint32_t r;
    asm("cvt.rn.bf16x2.f32 %0, %1, %2;" : "=r"(r) : "f"(hi), "f"(lo));
    return r;
}

// ---------------------------------------------------------------- K0a: split Q/K
__global__ __launch_bounds__(256) void split_kernel(const float* __restrict__ src, int which, int n) {
    __nv_bfloat16 *hi, *lo;
    if (which == 0) { hi = g_Qh; lo = g_Ql; }
    else            { hi = g_Kh; lo = g_Kl; }
    int i = blockIdx.x * blockDim.x + threadIdx.x;
    if (i < n) {
        float x = src[i];
        __nv_bfloat16 h = __float2bfloat16(x);
        hi[i] = h;
        lo[i] = __float2bfloat16(x - __bfloat162float(h));
    }
}

// ---------------------------------------------------------------- K0b: V transpose+split -> [b][d][k]
__global__ __launch_bounds__(256) void vtrans_kernel(const float* __restrict__ v) {
    __shared__ float t[32][33];
    int b = blockIdx.z, d0 = blockIdx.y * 32, k0 = blockIdx.x * 32;
    int tx = threadIdx.x, ty = threadIdx.y;   // block (32,8)
    #pragma unroll
    for (int j = 0; j < 32; j += 8)
        t[ty + j][tx] = v[((size_t)b * L_ + k0 + ty + j) * D_ + d0 + tx];
    __syncthreads();
    #pragma unroll
    for (int j = 0; j < 32; j += 8) {
        float x = t[tx][ty + j];
        int d = d0 + ty + j;
        size_t o = ((size_t)b * D_ + d) * L_ + k0 + tx;
        __nv_bfloat16 h = __float2bfloat16(x);
        g_VhT[o] = h;
        g_VlT[o] = __float2bfloat16(x - __bfloat162float(h));
    }
}

// ---------------- K1: fused — scores GEMM + exp + mask + u-write + AV + I
// grid (L/64, B), block 128 (4 warps x 16 q-rows). Dyn smem 65536B (3 CTAs/SM).
// Swizzled tiles: 64 rows x 128B, chunk c at byte ((c)^(r&7))*16.
// layout: QH 0, QL 8192, K[2]: KH 16384+d*16384, KL +8192, VH 49152, VL 57344
__global__ __launch_bounds__(128, 3) void main_kernel(const int* __restrict__ mask,
                                                      float* __restrict__ attn,
                                                      float* __restrict__ out) {
    extern __shared__ char smem[];
    const int QH = 0, QL = 8192, KB0 = 16384, VH = 49152, VL = 57344;
    int b = blockIdx.y, m0 = blockIdx.x * 64, tid = threadIdx.x;
    int warp = tid >> 5, lane = tid & 31, gid = lane >> 2, tig = lane & 3;
    uint32_t sm = smem_u32(smem);

    // ---- prologue: Q + K0 (group0), V0 (group1)
    {
        size_t qoff = ((size_t)b * L_ + m0) * D_;
        size_t koff = ((size_t)b * L_) * D_;
        #pragma unroll
        for (int it = 0; it < 4; it++) {
            int i = tid + it * 128, r = i >> 3, c = i & 7;
            uint32_t o = r * 128 + ((c ^ (r & 7)) * 16);
            cp16(sm + QH + o, g_Qh + qoff + r * 64 + c * 8);
            cp16(sm + QL + o, g_Ql + qoff + r * 64 + c * 8);
            cp16(sm + KB0 + o,        g_Kh + koff + r * 64 + c * 8);
            cp16(sm + KB0 + 8192 + o, g_Kl + koff + r * 64 + c * 8);
        }
        cp_commit();
        #pragma unroll
        for (int it = 0; it < 4; it++) {
            int i = tid + it * 128, r = i >> 3, c = i & 7;
            uint32_t o = r * 128 + ((c ^ (r & 7)) * 16);
            cp16(sm + VH + o, g_VhT + ((size_t)b * D_ + r) * L_ + c * 8);
            cp16(sm + VL + o, g_VlT + ((size_t)b * D_ + r) * L_ + c * 8);
        }
        cp_commit();
    }

    // fragment addressing (swizzled): row&7 == lane&7 for all fragments here
    uint32_t sw = lane & 7;
    uint32_t cA = lane >> 4;            // 0/1
    uint32_t cB = (lane >> 3) & 1;      // 0/1
    int rA = warp * 16 + (lane & 15);
    uint32_t aQh = sm + QH + rA * 128, aQl = sm + QL + rA * 128;
    uint32_t rowBoff[4];
    #pragma unroll
    for (int g = 0; g < 4; g++)
        rowBoff[g] = (uint32_t)((g * 16 + ((lane >> 4) & 1) * 8 + (lane & 7)) * 128);

    int r0 = warp * 16 + gid, r1 = r0 + 8;
    const int* mrow0 = mask + ((size_t)(b * L_ + m0 + r0)) * L_ + tig * 2;
    const int* mrow1 = mask + ((size_t)(b * L_ + m0 + r1)) * L_ + tig * 2;

    float accO[8][4];
    #pragma unroll
    for (int j = 0; j < 8; j++)
        #pragma unroll
        for (int x = 0; x < 4; x++) accO[j][x] = 0.f;

    float rsa0 = 0.f, rsa1 = 0.f, rsu0 = 0.f, rsu1 = 0.f;

    for (int kt = 0; kt < 32; kt++) {
        int d = kt & 1, n0 = kt * 64;
        cp_wait1();                 // K(kt) (+Q on iter 0) ready; V(kt) may fly
        __syncthreads();

        // mask prefetch into registers (covered by scores GEMM)
        int2 mk0[8], mk1[8];
        #pragma unroll
        for (int j = 0; j < 8; j++) {
            mk0[j] = __ldg((const int2*)(mrow0 + n0 + j*8));
            mk1[j] = __ldg((const int2*)(mrow1 + n0 + j*8));
        }

        if (kt < 31) {              // prefetch K(kt+1)
            int d2 = (kt + 1) & 1, n2 = (kt + 1) * 64;
            size_t koff = ((size_t)b * L_ + n2) * D_;
            #pragma unroll
            for (int it = 0; it < 4; it++) {
                int i = tid + it * 128, r = i >> 3, c = i & 7;
                uint32_t o = r * 128 + ((c ^ (r & 7)) * 16);
                cp16(sm + KB0 + d2 * 16384 + o,        g_Kh + koff + r * 64 + c * 8);
                cp16(sm + KB0 + d2 * 16384 + 8192 + o, g_Kl + koff + r * 64 + c * 8);
            }
            cp_commit();
        }

        // ---- scores: S(16x64) = Q_warp · K^T  (3-product bf16 split)
        float accS[8][4];
        #pragma unroll
        for (int j = 0; j < 8; j++)
            #pragma unroll
            for (int x = 0; x < 4; x++) accS[j][x] = 0.f;

        uint32_t kh_base = sm + KB0 + d * 16384, kl_base = kh_base + 8192;
        #pragma unroll
        for (int kk = 0; kk < 4; kk++) {
            uint32_t oA = ((cA + 2*kk) ^ sw) * 16;
            uint32_t oB = ((cB + 2*kk) ^ sw) * 16;
            uint32_t ah[4], al[4];
            ldsm_x4(ah[0], ah[1], ah[2], ah[3], aQh + oA);
            ldsm_x4(al[0], al[1], al[2], al[3], aQl + oA);
            #pragma unroll
            for (int g = 0; g < 4; g++) {
                uint32_t bh[4], bl[4];
                ldsm_x4(bh[0], bh[1], bh[2], bh[3], kh_base + rowBoff[g] + oB);
                ldsm_x4(bl[0], bl[1], bl[2], bl[3], kl_base + rowBoff[g] + oB);
                #pragma unroll
                for (int h = 0; h < 2; h++) {
                    int j = g*2 + h;
                    mma_bf16(accS[j], ah[0], ah[1], ah[2], ah[3], bh[h*2], bh[h*2+1]);
                    mma_bf16(accS[j], ah[0], ah[1], ah[2], ah[3], bl[h*2], bl[h*2+1]);
                    mma_bf16(accS[j], al[0], al[1], al[2], al[3], bh[h*2], bh[h*2+1]);
                }
            }
        }

        // ---- epilogue: exp, mask, sums, write unscaled u, pack bf16 hi/lo
        uint32_t u0[8], u1[8], l0[8], l1[8];
        #pragma unroll
        for (int j = 0; j < 8; j++) {
            int c = j*8 + tig*2;
            float e0 = exp2f(accS[j][0] * CE);
            float e1 = exp2f(accS[j][1] * CE);
            float e2 = exp2f(accS[j][2] * CE);
            float e3 = exp2f(accS[j][3] * CE);
            rsa0 += e0 + e1;
            rsa1 += e2 + e3;
            float a0 = mk0[j].x ? 0.f : e0;
            float a1 = mk0[j].y ? 0.f : e1;
            float a2 = mk1[j].x ? 0.f : e2;
            float a3 = mk1[j].y ? 0.f : e3;
            rsu0 += a0 + a1;
            rsu1 += a2 + a3;
            *(float2*)(attn + ((size_t)b * L_ + m0 + r0) * L_ + n0 + c) = make_float2(a0, a1);
            *(float2*)(attn + ((size_t)b * L_ + m0 + r1) * L_ + n0 + c) = make_float2(a2, a3);
            u0[j] = pack_bf16(a0, a1);
            u1[j] = pack_bf16(a2, a3);
            float h0 = __bfloat162float(__float2bfloat16(a0));
            float h1 = __bfloat162float(__float2bfloat16(a1));
            float h2 = __bfloat162float(__float2bfloat16(a2));
            float h3 = __bfloat162float(__float2bfloat16(a3));
            l0[j] = pack_bf16(a0 - h0, a1 - h1);
            l1[j] = pack_bf16(a2 - h2, a3 - h3);
        }

        // ---- wait V(kt), then AV
        if (kt < 31) cp_wait1(); else cp_wait0();
        __syncthreads();

        #pragma unroll
        for (int kc = 0; kc < 4; kc++) {
            uint32_t oB = ((cB + 2*kc) ^ sw) * 16;
            uint32_t pa0 = u0[2*kc], pa1 = u1[2*kc], pa2 = u0[2*kc+1], pa3 = u1[2*kc+1];
            uint32_t qa0 = l0[2*kc], qa1 = l1[2*kc], qa2 = l0[2*kc+1], qa3 = l1[2*kc+1];
            #pragma unroll
            for (int g = 0; g < 4; g++) {
                uint32_t vh[4], vl[4];
                ldsm_x4(vh[0], vh[1], vh[2], vh[3], sm + VH + rowBoff[g] + oB);
                ldsm_x4(vl[0], vl[1], vl[2], vl[3], sm + VL + rowBoff[g] + oB);
                #pragma unroll
                for (int h = 0; h < 2; h++) {
                    int j = g*2 + h;
                    mma_bf16(accO[j], pa0, pa1, pa2, pa3, vh[h*2], vh[h*2+1]);
                    mma_bf16(accO[j], pa0, pa1, pa2, pa3, vl[h*2], vl[h*2+1]);
                    mma_bf16(accO[j], qa0, qa1, qa2, qa3, vh[h*2], vh[h*2+1]);
                }
            }
        }
        __syncthreads();            // all warps done reading V

        if (kt < 31) {              // prefetch V(kt+1) into the single V buffer
            int n2 = (kt + 1) * 64;
            #pragma unroll
            for (int it = 0; it < 4; it++) {
                int i = tid + it * 128, r = i >> 3, c = i & 7;
                uint32_t o = r * 128 + ((c ^ (r & 7)) * 16);
                cp16(sm + VH + o, g_VhT + ((size_t)b * D_ + r) * L_ + n2 + c * 8);
                cp16(sm + VL + o, g_VlT + ((size_t)b * D_ + r) * L_ + n2 + c * 8);
            }
            cp_commit();
        }
    }

    // ---- denominators: butterfly over tig lanes
    #pragma unroll
    for (int o = 1; o <= 2; o <<= 1) {
        rsa0 += __shfl_xor_sync(0xffffffffu, rsa0, o);
        rsa1 += __shfl_xor_sync(0xffffffffu, rsa1, o);
        rsu0 += __shfl_xor_sync(0xffffffffu, rsu0, o);
        rsu1 += __shfl_xor_sync(0xffffffffu, rsu1, o);
    }
    float I0 = 1.f / (rsu0 + 1e-8f * rsa0);
    float I1 = 1.f / (rsu1 + 1e-8f * rsa1);
    if (tig == 0) {
        g_I[b * L_ + m0 + r0] = I0;
        g_I[b * L_ + m0 + r1] = I1;
    }

    // ---- out epilogue: O = O_u * I
    #pragma unroll
    for (int j = 0; j < 8; j++) {
        int c = j*8 + tig*2;
        *(float2*)(out + ((size_t)b * L_ + m0 + r0) * D_ + c) =
            make_float2(accO[j][0] * I0, accO[j][1] * I0);
        *(float2*)(out + ((size_t)b * L_ + m0 + r1) * D_ + c) =
            make_float2(accO[j][2] * I1, accO[j][3] * I1);
    }
}

// ---------------- K2: rescale attn rows by I (streaming, one CTA per row)
__global__ __launch_bounds__(256) void rescale_kernel(float* __restrict__ attn) {
    int row = blockIdx.x;
    float inv = g_I[row];
    float4* p = (float4*)(attn + (size_t)row * L_);
    int tid = threadIdx.x;
    #pragma unroll
    for (int it = 0; it < 2; it++) {
        float4 v = p[tid + it * 256];
        v.x *= inv; v.y *= inv; v.z *= inv; v.w *= inv;
        p[tid + it * 256] = v;
    }
}

// ----------------------------------------------------------------- launcher
extern "C" void kernel_launch(void* const* d_in, const int* in_sizes, int n_in,
                              void* d_out, int out_size) {
    const float* q = (const float*)d_in[0];
    const float* k = (const float*)d_in[1];
    const float* v = (const float*)d_in[2];
    const int* mask = (const int*)d_in[3];
    float* out  = (float*)d_out;
    float* attn = out + (size_t)B_ * L_ * D_;

    cudaFuncSetAttribute(main_kernel, cudaFuncAttributeMaxDynamicSharedMemorySize, 65536);

    int n = NE, nb = (n + 255) / 256;
    split_kernel<<<nb, 256>>>(q, 0, n);
    split_kernel<<<nb, 256>>>(k, 1, n);
    vtrans_kernel<<<dim3(L_/32, 2, B_), dim3(32, 8)>>>(v);

    main_kernel<<<dim3(L_/64, B_), 128, 65536>>>(mask, attn, out);
    rescale_kernel<<<B_*L_, 256>>>(attn);
}

// round 8
// speedup vs baseline: 1.3120x; 1.1108x over previous
#include <cuda_runtime.h>
#include <cuda_bf16.h>
#include <cstdint>

#define B_ 16
#define L_ 2048
#define D_ 64
#define NE (B_*L_*D_)
#define CE 0.18033688011112042f     // (1/8)*log2(e)

// device scratch (no allocation)
__device__ __nv_bfloat16 g_Qh[NE], g_Ql[NE];
__device__ __nv_bfloat16 g_Kh[NE], g_Kl[NE];
__device__ __nv_bfloat16 g_VhT[NE], g_VlT[NE];        // [b][d][k]
__device__ float g_I[B_*L_];                          // per-row 1/denom

// ---------------------------------------------------------------- helpers
__device__ __forceinline__ uint32_t smem_u32(const void* p) {
    return (uint32_t)__cvta_generic_to_shared(p);
}
__device__ __forceinline__ void cp16(uint32_t dst, const void* src) {
    asm volatile("cp.async.cg.shared.global [%0], [%1], 16;" :: "r"(dst), "l"(src));
}
__device__ __forceinline__ void cp_commit() { asm volatile("cp.async.commit_group;"); }
__device__ __forceinline__ void cp_wait0()  { asm volatile("cp.async.wait_group 0;"); }

__device__ __forceinline__ void ldsm_x4(uint32_t& r0, uint32_t& r1, uint32_t& r2, uint32_t& r3,
                                        uint32_t addr) {
    asm volatile("ldmatrix.sync.aligned.m8n8.x4.shared.b16 {%0,%1,%2,%3}, [%4];"
                 : "=r"(r0), "=r"(r1), "=r"(r2), "=r"(r3) : "r"(addr));
}
__device__ __forceinline__ void mma_bf16(float* c,
                                         uint32_t a0, uint32_t a1, uint32_t a2, uint32_t a3,
                                         uint32_t b0, uint32_t b1) {
    asm volatile(
        "mma.sync.aligned.m16n8k16.row.col.f32.bf16.bf16.f32 "
        "{%0,%1,%2,%3}, {%4,%5,%6,%7}, {%8,%9}, {%0,%1,%2,%3};\n"
        : "+f"(c[0]), "+f"(c[1]), "+f"(c[2]), "+f"(c[3])
        : "r"(a0), "r"(a1), "r"(a2), "r"(a3), "r"(b0), "r"(b1));
}
// packed: upper16 = bf16(a) [hi part], lower16 = bf16(a - hi) [lo part]
__device__ __forceinline__ uint32_t packhl(float a) {
    __nv_bfloat16 h = __float2bfloat16(a);
    float res = a - __bfloat162float(h);
    uint32_t r;
    asm("cvt.rn.bf16x2.f32 %0, %1, %2;" : "=r"(r) : "f"(a), "f"(res));
    return r;
}

// ---------------------------------------------------------------- K0a: split Q/K
__global__ __launch_bounds__(256) void split_kernel(const float* __restrict__ src, int which, int n) {
    __nv_bfloat16 *hi, *lo;
    if (which == 0) { hi = g_Qh; lo = g_Ql; }
    else            { hi = g_Kh; lo = g_Kl; }
    int i = blockIdx.x * blockDim.x + threadIdx.x;
    if (i < n) {
        float x = src[i];
        __nv_bfloat16 h = __float2bfloat16(x);
        hi[i] = h;
        lo[i] = __float2bfloat16(x - __bfloat162float(h));
    }
}

// ---------------------------------------------------------------- K0b: V transpose+split -> [b][d][k]
__global__ __launch_bounds__(256) void vtrans_kernel(const float* __restrict__ v) {
    __shared__ float t[32][33];
    int b = blockIdx.z, d0 = blockIdx.y * 32, k0 = blockIdx.x * 32;
    int tx = threadIdx.x, ty = threadIdx.y;   // block (32,8)
    #pragma unroll
    for (int j = 0; j < 32; j += 8)
        t[ty + j][tx] = v[((size_t)b * L_ + k0 + ty + j) * D_ + d0 + tx];
    __syncthreads();
    #pragma unroll
    for (int j = 0; j < 32; j += 8) {
        float x = t[tx][ty + j];
        int d = d0 + ty + j;
        size_t o = ((size_t)b * D_ + d) * L_ + k0 + tx;
        __nv_bfloat16 h = __float2bfloat16(x);
        g_VhT[o] = h;
        g_VlT[o] = __float2bfloat16(x - __bfloat162float(h));
    }
}

// ---------------- K1: scores GEMM + exp + mask + row sums; writes packed hi/lo u
// grid (L/64, B), block 128 (4 warps x 16 rows). Dyn smem 49152B -> 4 CTAs/SM.
// layout: QH 0, QL 8192, K[d]: KH 16384+d*16384, KL +8192
__global__ __launch_bounds__(128, 4) void scores_kernel(const int* __restrict__ mask,
                                                        uint32_t* __restrict__ uout) {
    extern __shared__ char smem[];
    const int QH = 0, QL = 8192, KB0 = 16384;
    int b = blockIdx.y, m0 = blockIdx.x * 64, tid = threadIdx.x;
    int warp = tid >> 5, lane = tid & 31, gid = lane >> 2, tig = lane & 3;
    uint32_t sm = smem_u32(smem);

    // prologue: Q + K0 (one group)
    {
        size_t qoff = ((size_t)b * L_ + m0) * D_;
        size_t koff = ((size_t)b * L_) * D_;
        #pragma unroll
        for (int it = 0; it < 4; it++) {
            int i = tid + it * 128, r = i >> 3, c = i & 7;
            uint32_t o = r * 128 + ((c ^ (r & 7)) * 16);
            cp16(sm + QH + o, g_Qh + qoff + r * 64 + c * 8);
            cp16(sm + QL + o, g_Ql + qoff + r * 64 + c * 8);
            cp16(sm + KB0 + o,        g_Kh + koff + r * 64 + c * 8);
            cp16(sm + KB0 + 8192 + o, g_Kl + koff + r * 64 + c * 8);
        }
        cp_commit();
    }

    uint32_t sw = lane & 7;
    uint32_t cA = lane >> 4;
    uint32_t cB = (lane >> 3) & 1;
    int rA = warp * 16 + (lane & 15);
    uint32_t aQh = sm + QH + rA * 128, aQl = sm + QL + rA * 128;
    uint32_t rowBoff[4];
    #pragma unroll
    for (int g = 0; g < 4; g++)
        rowBoff[g] = (uint32_t)((g * 16 + ((lane >> 4) & 1) * 8 + (lane & 7)) * 128);

    int r0 = warp * 16 + gid, r1 = r0 + 8;
    const int* mrow0 = mask + ((size_t)(b * L_ + m0 + r0)) * L_ + tig * 2;
    const int* mrow1 = mask + ((size_t)(b * L_ + m0 + r1)) * L_ + tig * 2;

    float rsa0 = 0.f, rsa1 = 0.f, rsu0 = 0.f, rsu1 = 0.f;

    for (int kt = 0; kt < 32; kt++) {
        int d = kt & 1, n0 = kt * 64;
        cp_wait0();
        __syncthreads();

        // mask prefetch into registers (latency covered by scores GEMM)
        int2 mk0[8], mk1[8];
        #pragma unroll
        for (int j = 0; j < 8; j++) {
            mk0[j] = __ldg((const int2*)(mrow0 + n0 + j*8));
            mk1[j] = __ldg((const int2*)(mrow1 + n0 + j*8));
        }

        if (kt < 31) {              // prefetch K(kt+1)
            int d2 = (kt + 1) & 1, n2 = (kt + 1) * 64;
            size_t koff = ((size_t)b * L_ + n2) * D_;
            #pragma unroll
            for (int it = 0; it < 4; it++) {
                int i = tid + it * 128, r = i >> 3, c = i & 7;
                uint32_t o = r * 128 + ((c ^ (r & 7)) * 16);
                cp16(sm + KB0 + d2 * 16384 + o,        g_Kh + koff + r * 64 + c * 8);
                cp16(sm + KB0 + d2 * 16384 + 8192 + o, g_Kl + koff + r * 64 + c * 8);
            }
            cp_commit();
        }

        // ---- scores: S(16x64) = Q_warp · K^T (3-product bf16 split)
        float accS[8][4];
        #pragma unroll
        for (int j = 0; j < 8; j++)
            #pragma unroll
            for (int x = 0; x < 4; x++) accS[j][x] = 0.f;

        uint32_t kh_base = sm + KB0 + d * 16384, kl_base = kh_base + 8192;
        #pragma unroll
        for (int kk = 0; kk < 4; kk++) {
            uint32_t oA = ((cA + 2*kk) ^ sw) * 16;
            uint32_t oB = ((cB + 2*kk) ^ sw) * 16;
            uint32_t ah[4], al[4];
            ldsm_x4(ah[0], ah[1], ah[2], ah[3], aQh + oA);
            ldsm_x4(al[0], al[1], al[2], al[3], aQl + oA);
            #pragma unroll
            for (int g = 0; g < 4; g++) {
                uint32_t bh[4], bl[4];
                ldsm_x4(bh[0], bh[1], bh[2], bh[3], kh_base + rowBoff[g] + oB);
                ldsm_x4(bl[0], bl[1], bl[2], bl[3], kl_base + rowBoff[g] + oB);
                #pragma unroll
                for (int h = 0; h < 2; h++) {
                    int j = g*2 + h;
                    mma_bf16(accS[j], ah[0], ah[1], ah[2], ah[3], bh[h*2], bh[h*2+1]);
                    mma_bf16(accS[j], ah[0], ah[1], ah[2], ah[3], bl[h*2], bl[h*2+1]);
                    mma_bf16(accS[j], al[0], al[1], al[2], al[3], bh[h*2], bh[h*2+1]);
                }
            }
        }

        // ---- epilogue: exp, mask, sums, write packed (hi,lo) u
        #pragma unroll
        for (int j = 0; j < 8; j++) {
            int c = j*8 + tig*2;
            float e0 = exp2f(accS[j][0] * CE);
            float e1 = exp2f(accS[j][1] * CE);
            float e2 = exp2f(accS[j][2] * CE);
            float e3 = exp2f(accS[j][3] * CE);
            rsa0 += e0 + e1;
            rsa1 += e2 + e3;
            float a0 = mk0[j].x ? 0.f : e0;
            float a1 = mk0[j].y ? 0.f : e1;
            float a2 = mk1[j].x ? 0.f : e2;
            float a3 = mk1[j].y ? 0.f : e3;
            rsu0 += a0 + a1;
            rsu1 += a2 + a3;
            uint2 p01 = make_uint2(packhl(a0), packhl(a1));
            uint2 p23 = make_uint2(packhl(a2), packhl(a3));
            *(uint2*)(uout + ((size_t)b * L_ + m0 + r0) * L_ + n0 + c) = p01;
            *(uint2*)(uout + ((size_t)b * L_ + m0 + r1) * L_ + n0 + c) = p23;
        }
    }

    // ---- denominators: butterfly over tig lanes
    #pragma unroll
    for (int o = 1; o <= 2; o <<= 1) {
        rsa0 += __shfl_xor_sync(0xffffffffu, rsa0, o);
        rsa1 += __shfl_xor_sync(0xffffffffu, rsa1, o);
        rsu0 += __shfl_xor_sync(0xffffffffu, rsu0, o);
        rsu1 += __shfl_xor_sync(0xffffffffu, rsu1, o);
    }
    if (tig == 0) {
        g_I[b * L_ + m0 + r0] = 1.f / (rsu0 + 1e-8f * rsa0);
        g_I[b * L_ + m0 + r1] = 1.f / (rsu1 + 1e-8f * rsa1);
    }
}

// ---------------- K2: read packed u -> attn=(hi+lo)*I write + O = u@V
// grid (L/64, B), block 128. Dyn smem 51456B -> 4 CTAs/SM.
// layout: U[d] 0+d*17408 (64 rows x 272B), VH 34816, VL 43008, SI 51200
__global__ __launch_bounds__(128, 4) void av_kernel(const uint32_t* __restrict__ uin,
                                                    float* __restrict__ attn,
                                                    float* __restrict__ out) {
    extern __shared__ char smem[];
    const int UB = 0, VH = 34816, VL = 43008, SI = 51200;
    int b = blockIdx.y, m0 = blockIdx.x * 64, tid = threadIdx.x;
    int warp = tid >> 5, lane = tid & 31, gid = lane >> 2, tig = lane & 3;
    uint32_t sm = smem_u32(smem);
    float* sI = (float*)(smem + SI);

    if (tid < 64) sI[tid] = g_I[b * L_ + m0 + tid];

    // prologue: U(0) then V(0)
    {
        const uint32_t* ub = uin + ((size_t)b * L_ + m0) * L_;
        #pragma unroll
        for (int it = 0; it < 8; it++) {
            int i = tid + it * 128, r = i >> 4, c = i & 15;
            cp16(sm + UB + r * 272 + c * 16, ub + (size_t)r * L_ + c * 4);
        }
        cp_commit();
        #pragma unroll
        for (int it = 0; it < 4; it++) {
            int i = tid + it * 128, r = i >> 3, c = i & 7;
            uint32_t o = r * 128 + ((c ^ (r & 7)) * 16);
            cp16(sm + VH + o, g_VhT + ((size_t)b * D_ + r) * L_ + c * 8);
            cp16(sm + VL + o, g_VlT + ((size_t)b * D_ + r) * L_ + c * 8);
        }
        cp_commit();
    }

    uint32_t sw = lane & 7;
    uint32_t cB = (lane >> 3) & 1;
    uint32_t rowBoff[4];
    #pragma unroll
    for (int g = 0; g < 4; g++)
        rowBoff[g] = (uint32_t)((g * 16 + ((lane >> 4) & 1) * 8 + (lane & 7)) * 128);

    int r0 = warp * 16 + gid, r1 = r0 + 8;

    float accO[8][4];
    #pragma unroll
    for (int j = 0; j < 8; j++)
        #pragma unroll
        for (int x = 0; x < 4; x++) accO[j][x] = 0.f;

    for (int kt = 0; kt < 32; kt++) {
        int d = kt & 1, n0 = kt * 64;
        cp_wait0();
        __syncthreads();

        if (kt < 31) {              // prefetch U(kt+1)
            int d2 = (kt + 1) & 1, n2 = (kt + 1) * 64;
            const uint32_t* ub = uin + ((size_t)b * L_ + m0) * L_ + n2;
            #pragma unroll
            for (int it = 0; it < 8; it++) {
                int i = tid + it * 128, r = i >> 4, c = i & 15;
                cp16(sm + UB + d2 * 17408 + r * 272 + c * 16, ub + (size_t)r * L_ + c * 4);
            }
            cp_commit();
        }

        float I0 = sI[r0], I1 = sI[r1];

        // ---- fragments from packed u + attn write
        uint32_t u0[8], u1[8], l0[8], l1[8];
        const char* ubase = smem + UB + d * 17408;
        #pragma unroll
        for (int j = 0; j < 8; j++) {
            int c = j*8 + tig*2;
            uint2 q0 = *(const uint2*)(ubase + r0 * 272 + c * 4);
            uint2 q1 = *(const uint2*)(ubase + r1 * 272 + c * 4);
            u0[j] = __byte_perm(q0.x, q0.y, 0x7632);   // hi halves (cols c, c+1)
            l0[j] = __byte_perm(q0.x, q0.y, 0x5410);   // lo halves
            u1[j] = __byte_perm(q1.x, q1.y, 0x7632);
            l1[j] = __byte_perm(q1.x, q1.y, 0x5410);
            float a00 = __uint_as_float(q0.x & 0xffff0000u) + __uint_as_float(q0.x << 16);
            float a01 = __uint_as_float(q0.y & 0xffff0000u) + __uint_as_float(q0.y << 16);
            float a10 = __uint_as_float(q1.x & 0xffff0000u) + __uint_as_float(q1.x << 16);
            float a11 = __uint_as_float(q1.y & 0xffff0000u) + __uint_as_float(q1.y << 16);
            *(float2*)(attn + ((size_t)b * L_ + m0 + r0) * L_ + n0 + c) =
                make_float2(a00 * I0, a01 * I0);
            *(float2*)(attn + ((size_t)b * L_ + m0 + r1) * L_ + n0 + c) =
                make_float2(a10 * I1, a11 * I1);
        }

        // ---- AV: O_u += u · V (3-product)
        #pragma unroll
        for (int kc = 0; kc < 4; kc++) {
            uint32_t oB = ((cB + 2*kc) ^ sw) * 16;
            uint32_t pa0 = u0[2*kc], pa1 = u1[2*kc], pa2 = u0[2*kc+1], pa3 = u1[2*kc+1];
            uint32_t qa0 = l0[2*kc], qa1 = l1[2*kc], qa2 = l0[2*kc+1], qa3 = l1[2*kc+1];
            #pragma unroll
            for (int g = 0; g < 4; g++) {
                uint32_t vh[4], vl[4];
                ldsm_x4(vh[0], vh[1], vh[2], vh[3], sm + VH + rowBoff[g] + oB);
                ldsm_x4(vl[0], vl[1], vl[2], vl[3], sm + VL + rowBoff[g] + oB);
                #pragma unroll
                for (int h = 0; h < 2; h++) {
                    int j = g*2 + h;
                    mma_bf16(accO[j], pa0, pa1, pa2, pa3, vh[h*2], vh[h*2+1]);
                    mma_bf16(accO[j], pa0, pa1, pa2, pa3, vl[h*2], vl[h*2+1]);
                    mma_bf16(accO[j], qa0, qa1, qa2, qa3, vh[h*2], vh[h*2+1]);
                }
            }
        }
        __syncthreads();            // all warps done reading V(kt)

        if (kt < 31) {              // prefetch V(kt+1) into the single V buffer
            int n2 = (kt + 1) * 64;
            #pragma unroll
            for (int it = 0; it < 4; it++) {
                int i = tid + it * 128, r = i >> 3, c = i & 7;
                uint32_t o = r * 128 + ((c ^ (r & 7)) * 16);
                cp16(sm + VH + o, g_VhT + ((size_t)b * D_ + r) * L_ + n2 + c * 8);
                cp16(sm + VL + o, g_VlT + ((size_t)b * D_ + r) * L_ + n2 + c * 8);
            }
            cp_commit();
        }
    }

    // ---- out epilogue: O = O_u * I
    float I0 = sI[r0], I1 = sI[r1];
    #pragma unroll
    for (int j = 0; j < 8; j++) {
        int c = j*8 + tig*2;
        *(float2*)(out + ((size_t)b * L_ + m0 + r0) * D_ + c) =
            make_float2(accO[j][0] * I0, accO[j][1] * I0);
        *(float2*)(out + ((size_t)b * L_ + m0 + r1) * D_ + c) =
            make_float2(accO[j][2] * I1, accO[j][3] * I1);
    }
}

// ----------------------------------------------------------------- launcher
extern "C" void kernel_launch(void* const* d_in, const int* in_sizes, int n_in,
                              void* d_out, int out_size) {
    const float* q = (const float*)d_in[0];
    const float* k = (const float*)d_in[1];
    const float* v = (const float*)d_in[2];
    const int* mask = (const int*)d_in[3];
    float* out  = (float*)d_out;
    float* attn = out + (size_t)B_ * L_ * D_;

    cudaFuncSetAttribute(scores_kernel, cudaFuncAttributeMaxDynamicSharedMemorySize, 49152);
    cudaFuncSetAttribute(av_kernel,     cudaFuncAttributeMaxDynamicSharedMemorySize, 51456);

    int n = NE, nb = (n + 255) / 256;
    split_kernel<<<nb, 256>>>(q, 0, n);
    split_kernel<<<nb, 256>>>(k, 1, n);
    vtrans_kernel<<<dim3(L_/32, 2, B_), dim3(32, 8)>>>(v);

    scores_kernel<<<dim3(L_/64, B_), 128, 49152>>>(mask, (uint32_t*)attn);
    av_kernel<<<dim3(L_/64, B_), 128, 51456>>>((const uint32_t*)attn, attn, out);
}

// round 9
// speedup vs baseline: 1.5038x; 1.1462x over previous
#include <cuda_runtime.h>
#include <cuda_bf16.h>
#include <cuda_fp16.h>
#include <cstdint>

#define B_ 16
#define L_ 2048
#define D_ 64
#define NE (B_*L_*D_)
#define CE 0.18033688011112042f     // (1/8)*log2(e)

// device scratch (no allocation)
__device__ __nv_bfloat16 g_Qh[NE], g_Ql[NE];
__device__ __nv_bfloat16 g_Kh[NE], g_Kl[NE];
__device__ __half g_VhT[NE], g_VlT[NE];               // [b][d][k], fp16 hi/lo
__device__ __half g_u[(size_t)B_*L_*L_];              // masked exponentials, fp16
__device__ float g_I[B_*L_];                          // per-row 1/denom

// ---------------------------------------------------------------- helpers
__device__ __forceinline__ uint32_t smem_u32(const void* p) {
    return (uint32_t)__cvta_generic_to_shared(p);
}
__device__ __forceinline__ void cp16(uint32_t dst, const void* src) {
    asm volatile("cp.async.cg.shared.global [%0], [%1], 16;" :: "r"(dst), "l"(src));
}
__device__ __forceinline__ void cp_commit() { asm volatile("cp.async.commit_group;"); }
__device__ __forceinline__ void cp_wait0()  { asm volatile("cp.async.wait_group 0;"); }

__device__ __forceinline__ void ldsm_x4(uint32_t& r0, uint32_t& r1, uint32_t& r2, uint32_t& r3,
                                        uint32_t addr) {
    asm volatile("ldmatrix.sync.aligned.m8n8.x4.shared.b16 {%0,%1,%2,%3}, [%4];"
                 : "=r"(r0), "=r"(r1), "=r"(r2), "=r"(r3) : "r"(addr));
}
__device__ __forceinline__ void mma_bf16(float* c,
                                         uint32_t a0, uint32_t a1, uint32_t a2, uint32_t a3,
                                         uint32_t b0, uint32_t b1) {
    asm volatile(
        "mma.sync.aligned.m16n8k16.row.col.f32.bf16.bf16.f32 "
        "{%0,%1,%2,%3}, {%4,%5,%6,%7}, {%8,%9}, {%0,%1,%2,%3};\n"
        : "+f"(c[0]), "+f"(c[1]), "+f"(c[2]), "+f"(c[3])
        : "r"(a0), "r"(a1), "r"(a2), "r"(a3), "r"(b0), "r"(b1));
}
__device__ __forceinline__ void mma_f16(float* c,
                                        uint32_t a0, uint32_t a1, uint32_t a2, uint32_t a3,
                                        uint32_t b0, uint32_t b1) {
    asm volatile(
        "mma.sync.aligned.m16n8k16.row.col.f32.f16.f16.f32 "
        "{%0,%1,%2,%3}, {%4,%5,%6,%7}, {%8,%9}, {%0,%1,%2,%3};\n"
        : "+f"(c[0]), "+f"(c[1]), "+f"(c[2]), "+f"(c[3])
        : "r"(a0), "r"(a1), "r"(a2), "r"(a3), "r"(b0), "r"(b1));
}

// ---------------------------------------------------------------- K0a: split Q/K (bf16 hi/lo)
__global__ __launch_bounds__(256) void split_kernel(const float* __restrict__ src, int which, int n) {
    __nv_bfloat16 *hi, *lo;
    if (which == 0) { hi = g_Qh; lo = g_Ql; }
    else            { hi = g_Kh; lo = g_Kl; }
    int i = blockIdx.x * blockDim.x + threadIdx.x;
    if (i < n) {
        float x = src[i];
        __nv_bfloat16 h = __float2bfloat16(x);
        hi[i] = h;
        lo[i] = __float2bfloat16(x - __bfloat162float(h));
    }
}

// ---------------------------------------------------------------- K0b: V transpose+split -> [b][d][k] fp16 hi/lo
__global__ __launch_bounds__(256) void vtrans_kernel(const float* __restrict__ v) {
    __shared__ float t[32][33];
    int b = blockIdx.z, d0 = blockIdx.y * 32, k0 = blockIdx.x * 32;
    int tx = threadIdx.x, ty = threadIdx.y;   // block (32,8)
    #pragma unroll
    for (int j = 0; j < 32; j += 8)
        t[ty + j][tx] = v[((size_t)b * L_ + k0 + ty + j) * D_ + d0 + tx];
    __syncthreads();
    #pragma unroll
    for (int j = 0; j < 32; j += 8) {
        float x = t[tx][ty + j];
        int d = d0 + ty + j;
        size_t o = ((size_t)b * D_ + d) * L_ + k0 + tx;
        __half h = __float2half_rn(x);
        g_VhT[o] = h;
        g_VlT[o] = __float2half_rn(x - __half2float(h));
    }
}

// ---------------- K1: scores GEMM + exp + mask + row sums; writes fp16 u
// grid (L/64, B), block 128 (4 warps x 16 rows). Dyn smem 49152B.
// layout: QH 0, QL 8192, K[d]: KH 16384+d*16384, KL +8192
__global__ __launch_bounds__(128, 4) void scores_kernel(const int* __restrict__ mask) {
    extern __shared__ char smem[];
    const int QH = 0, QL = 8192, KB0 = 16384;
    int b = blockIdx.y, m0 = blockIdx.x * 64, tid = threadIdx.x;
    int warp = tid >> 5, lane = tid & 31, gid = lane >> 2, tig = lane & 3;
    uint32_t sm = smem_u32(smem);

    // prologue: Q + K0 (one group)
    {
        size_t qoff = ((size_t)b * L_ + m0) * D_;
        size_t koff = ((size_t)b * L_) * D_;
        #pragma unroll
        for (int it = 0; it < 4; it++) {
            int i = tid + it * 128, r = i >> 3, c = i & 7;
            uint32_t o = r * 128 + ((c ^ (r & 7)) * 16);
            cp16(sm + QH + o, g_Qh + qoff + r * 64 + c * 8);
            cp16(sm + QL + o, g_Ql + qoff + r * 64 + c * 8);
            cp16(sm + KB0 + o,        g_Kh + koff + r * 64 + c * 8);
            cp16(sm + KB0 + 8192 + o, g_Kl + koff + r * 64 + c * 8);
        }
        cp_commit();
    }

    uint32_t sw = lane & 7;
    uint32_t cA = lane >> 4;
    uint32_t cB = (lane >> 3) & 1;
    int rA = warp * 16 + (lane & 15);
    uint32_t aQh = sm + QH + rA * 128, aQl = sm + QL + rA * 128;
    uint32_t rowBoff[4];
    #pragma unroll
    for (int g = 0; g < 4; g++)
        rowBoff[g] = (uint32_t)((g * 16 + ((lane >> 4) & 1) * 8 + (lane & 7)) * 128);

    int r0 = warp * 16 + gid, r1 = r0 + 8;
    const int* mrow0 = mask + ((size_t)(b * L_ + m0 + r0)) * L_ + tig * 2;
    const int* mrow1 = mask + ((size_t)(b * L_ + m0 + r1)) * L_ + tig * 2;

    float rsa0 = 0.f, rsa1 = 0.f, rsu0 = 0.f, rsu1 = 0.f;

    for (int kt = 0; kt < 32; kt++) {
        int d = kt & 1, n0 = kt * 64;
        cp_wait0();
        __syncthreads();

        // mask prefetch into registers (latency covered by scores GEMM)
        int2 mk0[8], mk1[8];
        #pragma unroll
        for (int j = 0; j < 8; j++) {
            mk0[j] = __ldg((const int2*)(mrow0 + n0 + j*8));
            mk1[j] = __ldg((const int2*)(mrow1 + n0 + j*8));
        }

        if (kt < 31) {              // prefetch K(kt+1)
            int d2 = (kt + 1) & 1, n2 = (kt + 1) * 64;
            size_t koff = ((size_t)b * L_ + n2) * D_;
            #pragma unroll
            for (int it = 0; it < 4; it++) {
                int i = tid + it * 128, r = i >> 3, c = i & 7;
                uint32_t o = r * 128 + ((c ^ (r & 7)) * 16);
                cp16(sm + KB0 + d2 * 16384 + o,        g_Kh + koff + r * 64 + c * 8);
                cp16(sm + KB0 + d2 * 16384 + 8192 + o, g_Kl + koff + r * 64 + c * 8);
            }
            cp_commit();
        }

        // ---- scores: S(16x64) = Q_warp · K^T (3-product bf16 split)
        float accS[8][4];
        #pragma unroll
        for (int j = 0; j < 8; j++)
            #pragma unroll
            for (int x = 0; x < 4; x++) accS[j][x] = 0.f;

        uint32_t kh_base = sm + KB0 + d * 16384, kl_base = kh_base + 8192;
        #pragma unroll
        for (int kk = 0; kk < 4; kk++) {
            uint32_t oA = ((cA + 2*kk) ^ sw) * 16;
            uint32_t oB = ((cB + 2*kk) ^ sw) * 16;
            uint32_t ah[4], al[4];
            ldsm_x4(ah[0], ah[1], ah[2], ah[3], aQh + oA);
            ldsm_x4(al[0], al[1], al[2], al[3], aQl + oA);
            #pragma unroll
            for (int g = 0; g < 4; g++) {
                uint32_t bh[4], bl[4];
                ldsm_x4(bh[0], bh[1], bh[2], bh[3], kh_base + rowBoff[g] + oB);
                ldsm_x4(bl[0], bl[1], bl[2], bl[3], kl_base + rowBoff[g] + oB);
                #pragma unroll
                for (int h = 0; h < 2; h++) {
                    int j = g*2 + h;
                    mma_bf16(accS[j], ah[0], ah[1], ah[2], ah[3], bh[h*2], bh[h*2+1]);
                    mma_bf16(accS[j], ah[0], ah[1], ah[2], ah[3], bl[h*2], bl[h*2+1]);
                    mma_bf16(accS[j], al[0], al[1], al[2], al[3], bh[h*2], bh[h*2+1]);
                }
            }
        }

        // ---- epilogue: exp, mask, sums, write fp16 u
        #pragma unroll
        for (int j = 0; j < 8; j++) {
            int c = j*8 + tig*2;
            float e0 = exp2f(accS[j][0] * CE);
            float e1 = exp2f(accS[j][1] * CE);
            float e2 = exp2f(accS[j][2] * CE);
            float e3 = exp2f(accS[j][3] * CE);
            rsa0 += e0 + e1;
            rsa1 += e2 + e3;
            float a0 = mk0[j].x ? 0.f : e0;
            float a1 = mk0[j].y ? 0.f : e1;
            float a2 = mk1[j].x ? 0.f : e2;
            float a3 = mk1[j].y ? 0.f : e3;
            rsu0 += a0 + a1;
            rsu1 += a2 + a3;
            *(__half2*)(g_u + ((size_t)b * L_ + m0 + r0) * L_ + n0 + c) = __floats2half2_rn(a0, a1);
            *(__half2*)(g_u + ((size_t)b * L_ + m0 + r1) * L_ + n0 + c) = __floats2half2_rn(a2, a3);
        }
    }

    // ---- denominators: butterfly over tig lanes
    #pragma unroll
    for (int o = 1; o <= 2; o <<= 1) {
        rsa0 += __shfl_xor_sync(0xffffffffu, rsa0, o);
        rsa1 += __shfl_xor_sync(0xffffffffu, rsa1, o);
        rsu0 += __shfl_xor_sync(0xffffffffu, rsu0, o);
        rsu1 += __shfl_xor_sync(0xffffffffu, rsu1, o);
    }
    if (tig == 0) {
        g_I[b * L_ + m0 + r0] = 1.f / (rsu0 + 1e-8f * rsa0);
        g_I[b * L_ + m0 + r1] = 1.f / (rsu1 + 1e-8f * rsa1);
    }
}

// ---------------- K2: read fp16 u -> attn=u*I write + O = u@V (fp16 mma)
// grid (L/64, B), block 128. Dyn smem 49408B.
// layout: U[d] 0+d*8192, VH[d] 16384+d*8192, VL[d] 32768+d*8192, SI 49152
__global__ __launch_bounds__(128, 4) void av_kernel(float* __restrict__ attn,
                                                    float* __restrict__ out) {
    extern __shared__ char smem[];
    const int UB = 0, VH = 16384, VL = 32768, SI = 49152;
    int b = blockIdx.y, m0 = blockIdx.x * 64, tid = threadIdx.x;
    int warp = tid >> 5, lane = tid & 31, gid = lane >> 2, tig = lane & 3;
    uint32_t sm = smem_u32(smem);
    float* sI = (float*)(smem + SI);

    if (tid < 64) sI[tid] = g_I[b * L_ + m0 + tid];

    // prologue: U(0), V(0)
    {
        const __half* ub = g_u + ((size_t)b * L_ + m0) * L_;
        #pragma unroll
        for (int it = 0; it < 4; it++) {
            int i = tid + it * 128, r = i >> 3, c = i & 7;
            uint32_t o = r * 128 + ((c ^ (r & 7)) * 16);
            cp16(sm + UB + o, ub + (size_t)r * L_ + c * 8);
            cp16(sm + VH + o, g_VhT + ((size_t)b * D_ + r) * L_ + c * 8);
            cp16(sm + VL + o, g_VlT + ((size_t)b * D_ + r) * L_ + c * 8);
        }
        cp_commit();
    }

    uint32_t sw = lane & 7;
    uint32_t cA = lane >> 4;
    uint32_t cB = (lane >> 3) & 1;
    int rA = warp * 16 + (lane & 15);
    uint32_t rowBoff[4];
    #pragma unroll
    for (int g = 0; g < 4; g++)
        rowBoff[g] = (uint32_t)((g * 16 + ((lane >> 4) & 1) * 8 + (lane & 7)) * 128);

    int r0 = warp * 16 + gid, r1 = r0 + 8;

    float accO[8][4];
    #pragma unroll
    for (int j = 0; j < 8; j++)
        #pragma unroll
        for (int x = 0; x < 4; x++) accO[j][x] = 0.f;

    float I0 = 0.f, I1 = 0.f;

    for (int kt = 0; kt < 32; kt++) {
        int d = kt & 1, n0 = kt * 64;
        cp_wait0();
        __syncthreads();
        if (kt == 0) { I0 = sI[r0]; I1 = sI[r1]; }

        if (kt < 31) {              // prefetch U,V(kt+1)
            int d2 = (kt + 1) & 1, n2 = (kt + 1) * 64;
            const __half* ub = g_u + ((size_t)b * L_ + m0) * L_ + n2;
            #pragma unroll
            for (int it = 0; it < 4; it++) {
                int i = tid + it * 128, r = i >> 3, c = i & 7;
                uint32_t o = r * 128 + ((c ^ (r & 7)) * 16);
                cp16(sm + UB + d2 * 8192 + o, ub + (size_t)r * L_ + c * 8);
                cp16(sm + VH + d2 * 8192 + o, g_VhT + ((size_t)b * D_ + r) * L_ + n2 + c * 8);
                cp16(sm + VL + d2 * 8192 + o, g_VlT + ((size_t)b * D_ + r) * L_ + n2 + c * 8);
            }
            cp_commit();
        }

        uint32_t aU = sm + UB + d * 8192 + rA * 128;
        uint32_t vh_base = sm + VH + d * 8192, vl_base = sm + VL + d * 8192;

        #pragma unroll
        for (int kk = 0; kk < 4; kk++) {
            uint32_t oA = ((cA + 2*kk) ^ sw) * 16;
            uint32_t oB = ((cB + 2*kk) ^ sw) * 16;
            uint32_t ua[4];
            ldsm_x4(ua[0], ua[1], ua[2], ua[3], aU + oA);

            // attn write: fragments -> float2 * I
            {
                int c = kk * 16 + tig * 2;
                float2 f0 = __half22float2(*(__half2*)&ua[0]);   // (r0, c)
                float2 f1 = __half22float2(*(__half2*)&ua[1]);   // (r1, c)
                float2 f2 = __half22float2(*(__half2*)&ua[2]);   // (r0, c+8)
                float2 f3 = __half22float2(*(__half2*)&ua[3]);   // (r1, c+8)
                size_t ro0 = ((size_t)b * L_ + m0 + r0) * L_ + n0;
                size_t ro1 = ((size_t)b * L_ + m0 + r1) * L_ + n0;
                *(float2*)(attn + ro0 + c)     = make_float2(f0.x * I0, f0.y * I0);
                *(float2*)(attn + ro1 + c)     = make_float2(f1.x * I1, f1.y * I1);
                *(float2*)(attn + ro0 + c + 8) = make_float2(f2.x * I0, f2.y * I0);
                *(float2*)(attn + ro1 + c + 8) = make_float2(f3.x * I1, f3.y * I1);
            }

            #pragma unroll
            for (int g = 0; g < 4; g++) {
                uint32_t vh[4], vl[4];
                ldsm_x4(vh[0], vh[1], vh[2], vh[3], vh_base + rowBoff[g] + oB);
                ldsm_x4(vl[0], vl[1], vl[2], vl[3], vl_base + rowBoff[g] + oB);
                #pragma unroll
                for (int h = 0; h < 2; h++) {
                    int j = g*2 + h;
                    mma_f16(accO[j], ua[0], ua[1], ua[2], ua[3], vh[h*2], vh[h*2+1]);
                    mma_f16(accO[j], ua[0], ua[1], ua[2], ua[3], vl[h*2], vl[h*2+1]);
                }
            }
        }
    }

    // ---- out epilogue: O = O_u * I
    #pragma unroll
    for (int j = 0; j < 8; j++) {
        int c = j*8 + tig*2;
        *(float2*)(out + ((size_t)b * L_ + m0 + r0) * D_ + c) =
            make_float2(accO[j][0] * I0, accO[j][1] * I0);
        *(float2*)(out + ((size_t)b * L_ + m0 + r1) * D_ + c) =
            make_float2(accO[j][2] * I1, accO[j][3] * I1);
    }
}

// ----------------------------------------------------------------- launcher
extern "C" void kernel_launch(void* const* d_in, const int* in_sizes, int n_in,
                              void* d_out, int out_size) {
    const float* q = (const float*)d_in[0];
    const float* k = (const float*)d_in[1];
    const float* v = (const float*)d_in[2];
    const int* mask = (const int*)d_in[3];
    float* out  = (float*)d_out;
    float* attn = out + (size_t)B_ * L_ * D_;

    cudaFuncSetAttribute(scores_kernel, cudaFuncAttributeMaxDynamicSharedMemorySize, 49152);
    cudaFuncSetAttribute(av_kernel,     cudaFuncAttributeMaxDynamicSharedMemorySize, 49408);

    int n = NE, nb = (n + 255) / 256;
    split_kernel<<<nb, 256>>>(q, 0, n);
    split_kernel<<<nb, 256>>>(k, 1, n);
    vtrans_kernel<<<dim3(L_/32, 2, B_), dim3(32, 8)>>>(v);

    scores_kernel<<<dim3(L_/64, B_), 128, 49152>>>(mask);
    av_kernel<<<dim3(L_/64, B_), 128, 49408>>>(attn, out);
}

// round 10
// speedup vs baseline: 1.5302x; 1.0176x over previous
#include <cuda_runtime.h>
#include <cuda_bf16.h>
#include <cuda_fp16.h>
#include <cstdint>

#define B_ 16
#define L_ 2048
#define D_ 64
#define NE (B_*L_*D_)
#define CE 0.18033688011112042f     // (1/8)*log2(e)

// device scratch (no allocation)
__device__ __nv_bfloat16 g_Qh[NE], g_Ql[NE];
__device__ __nv_bfloat16 g_Kh[NE], g_Kl[NE];
__device__ __half g_VhT[NE], g_VlT[NE];               // [b][d][k], fp16 hi/lo
__device__ __half g_u[(size_t)B_*L_*L_];              // u, tile-blocked swizzled 8KB tiles
__device__ float g_I[B_*L_];                          // per-row 1/denom

// ---------------------------------------------------------------- helpers
__device__ __forceinline__ uint32_t smem_u32(const void* p) {
    return (uint32_t)__cvta_generic_to_shared(p);
}
__device__ __forceinline__ void cp16(uint32_t dst, const void* src) {
    asm volatile("cp.async.cg.shared.global [%0], [%1], 16;" :: "r"(dst), "l"(src));
}
__device__ __forceinline__ void cp_commit() { asm volatile("cp.async.commit_group;"); }
__device__ __forceinline__ void cp_wait0()  { asm volatile("cp.async.wait_group 0;"); }

__device__ __forceinline__ void ldsm_x4(uint32_t& r0, uint32_t& r1, uint32_t& r2, uint32_t& r3,
                                        uint32_t addr) {
    asm volatile("ldmatrix.sync.aligned.m8n8.x4.shared.b16 {%0,%1,%2,%3}, [%4];"
                 : "=r"(r0), "=r"(r1), "=r"(r2), "=r"(r3) : "r"(addr));
}
__device__ __forceinline__ void mma_bf16(float* c,
                                         uint32_t a0, uint32_t a1, uint32_t a2, uint32_t a3,
                                         uint32_t b0, uint32_t b1) {
    asm volatile(
        "mma.sync.aligned.m16n8k16.row.col.f32.bf16.bf16.f32 "
        "{%0,%1,%2,%3}, {%4,%5,%6,%7}, {%8,%9}, {%0,%1,%2,%3};\n"
        : "+f"(c[0]), "+f"(c[1]), "+f"(c[2]), "+f"(c[3])
        : "r"(a0), "r"(a1), "r"(a2), "r"(a3), "r"(b0), "r"(b1));
}
__device__ __forceinline__ void mma_f16(float* c,
                                        uint32_t a0, uint32_t a1, uint32_t a2, uint32_t a3,
                                        uint32_t b0, uint32_t b1) {
    asm volatile(
        "mma.sync.aligned.m16n8k16.row.col.f32.f16.f16.f32 "
        "{%0,%1,%2,%3}, {%4,%5,%6,%7}, {%8,%9}, {%0,%1,%2,%3};\n"
        : "+f"(c[0]), "+f"(c[1]), "+f"(c[2]), "+f"(c[3])
        : "r"(a0), "r"(a1), "r"(a2), "r"(a3), "r"(b0), "r"(b1));
}

// ---------------------------------------------------------------- K0a: split Q/K (bf16 hi/lo)
__global__ __launch_bounds__(256) void split_kernel(const float* __restrict__ src, int which, int n) {
    __nv_bfloat16 *hi, *lo;
    if (which == 0) { hi = g_Qh; lo = g_Ql; }
    else            { hi = g_Kh; lo = g_Kl; }
    int i = blockIdx.x * blockDim.x + threadIdx.x;
    if (i < n) {
        float x = src[i];
        __nv_bfloat16 h = __float2bfloat16(x);
        hi[i] = h;
        lo[i] = __float2bfloat16(x - __bfloat162float(h));
    }
}

// ---------------------------------------------------------------- K0b: V transpose+split -> [b][d][k] fp16 hi/lo
__global__ __launch_bounds__(256) void vtrans_kernel(const float* __restrict__ v) {
    __shared__ float t[32][33];
    int b = blockIdx.z, d0 = blockIdx.y * 32, k0 = blockIdx.x * 32;
    int tx = threadIdx.x, ty = threadIdx.y;   // block (32,8)
    #pragma unroll
    for (int j = 0; j < 32; j += 8)
        t[ty + j][tx] = v[((size_t)b * L_ + k0 + ty + j) * D_ + d0 + tx];
    __syncthreads();
    #pragma unroll
    for (int j = 0; j < 32; j += 8) {
        float x = t[tx][ty + j];
        int d = d0 + ty + j;
        size_t o = ((size_t)b * D_ + d) * L_ + k0 + tx;
        __half h = __float2half_rn(x);
        g_VhT[o] = h;
        g_VlT[o] = __float2half_rn(x - __half2float(h));
    }
}

// ---------------- K1: scores GEMM + exp + mask + row sums; u staged in smem,
// written to gmem as tile-blocked swizzled 8KB tiles with STG.128.
// grid (L/64, B), block 128 (4 warps x 16 rows). Dyn smem 57344B (4 CTAs/SM).
// layout: QH 0, QL 8192, K[d]: 16384+d*16384 (KH) / +8192 (KL), US 49152
__global__ __launch_bounds__(128, 4) void scores_kernel(const int* __restrict__ mask) {
    extern __shared__ char smem[];
    const int QH = 0, QL = 8192, KB0 = 16384, US = 49152;
    int b = blockIdx.y, m0 = blockIdx.x * 64, tid = threadIdx.x;
    int warp = tid >> 5, lane = tid & 31, gid = lane >> 2, tig = lane & 3;
    uint32_t sm = smem_u32(smem);

    // prologue: Q + K0 (one group)
    {
        size_t qoff = ((size_t)b * L_ + m0) * D_;
        size_t koff = ((size_t)b * L_) * D_;
        #pragma unroll
        for (int it = 0; it < 4; it++) {
            int i = tid + it * 128, r = i >> 3, c = i & 7;
            uint32_t o = r * 128 + ((c ^ (r & 7)) * 16);
            cp16(sm + QH + o, g_Qh + qoff + r * 64 + c * 8);
            cp16(sm + QL + o, g_Ql + qoff + r * 64 + c * 8);
            cp16(sm + KB0 + o,        g_Kh + koff + r * 64 + c * 8);
            cp16(sm + KB0 + 8192 + o, g_Kl + koff + r * 64 + c * 8);
        }
        cp_commit();
    }

    uint32_t sw = lane & 7;
    uint32_t cA = lane >> 4;
    uint32_t cB = (lane >> 3) & 1;
    int rA = warp * 16 + (lane & 15);
    uint32_t aQh = sm + QH + rA * 128, aQl = sm + QL + rA * 128;
    uint32_t rowBoff[4];
    #pragma unroll
    for (int g = 0; g < 4; g++)
        rowBoff[g] = (uint32_t)((g * 16 + ((lane >> 4) & 1) * 8 + (lane & 7)) * 128);

    int r0 = warp * 16 + gid, r1 = r0 + 8;
    const int* mrow0 = mask + ((size_t)(b * L_ + m0 + r0)) * L_ + tig * 2;
    const int* mrow1 = mask + ((size_t)(b * L_ + m0 + r1)) * L_ + tig * 2;

    // u staging addresses (swizzled within the 8KB tile)
    char* usr0 = smem + US + r0 * 128 + tig * 4;
    char* usr1 = smem + US + r1 * 128 + tig * 4;
    int swr0 = r0 & 7, swr1 = r1 & 7;
    // u tile-blocked gmem base for this CTA's row-block
    uint4* gUrow = (uint4*)(g_u + (((size_t)b * 32 + (m0 >> 6)) * 32) * 4096);

    float rsa0 = 0.f, rsa1 = 0.f, rsu0 = 0.f, rsu1 = 0.f;

    for (int kt = 0; kt < 32; kt++) {
        int d = kt & 1, n0 = kt * 64;
        cp_wait0();
        __syncthreads();   // K(kt) ready; also: all threads finished last tile's u STG-reads

        // mask prefetch into registers (latency covered by scores GEMM)
        int2 mk0[8], mk1[8];
        #pragma unroll
        for (int j = 0; j < 8; j++) {
            mk0[j] = __ldg((const int2*)(mrow0 + n0 + j*8));
            mk1[j] = __ldg((const int2*)(mrow1 + n0 + j*8));
        }

        if (kt < 31) {              // prefetch K(kt+1)
            int d2 = (kt + 1) & 1, n2 = (kt + 1) * 64;
            size_t koff = ((size_t)b * L_ + n2) * D_;
            #pragma unroll
            for (int it = 0; it < 4; it++) {
                int i = tid + it * 128, r = i >> 3, c = i & 7;
                uint32_t o = r * 128 + ((c ^ (r & 7)) * 16);
                cp16(sm + KB0 + d2 * 16384 + o,        g_Kh + koff + r * 64 + c * 8);
                cp16(sm + KB0 + d2 * 16384 + 8192 + o, g_Kl + koff + r * 64 + c * 8);
            }
            cp_commit();
        }

        // ---- scores: S(16x64) = Q_warp · K^T (3-product bf16 split)
        float accS[8][4];
        #pragma unroll
        for (int j = 0; j < 8; j++)
            #pragma unroll
            for (int x = 0; x < 4; x++) accS[j][x] = 0.f;

        uint32_t kh_base = sm + KB0 + d * 16384, kl_base = kh_base + 8192;
        #pragma unroll
        for (int kk = 0; kk < 4; kk++) {
            uint32_t oA = ((cA + 2*kk) ^ sw) * 16;
            uint32_t oB = ((cB + 2*kk) ^ sw) * 16;
            uint32_t ah[4], al[4];
            ldsm_x4(ah[0], ah[1], ah[2], ah[3], aQh + oA);
            ldsm_x4(al[0], al[1], al[2], al[3], aQl + oA);
            #pragma unroll
            for (int g = 0; g < 4; g++) {
                uint32_t bh[4], bl[4];
                ldsm_x4(bh[0], bh[1], bh[2], bh[3], kh_base + rowBoff[g] + oB);
                ldsm_x4(bl[0], bl[1], bl[2], bl[3], kl_base + rowBoff[g] + oB);
                #pragma unroll
                for (int h = 0; h < 2; h++) {
                    int j = g*2 + h;
                    mma_bf16(accS[j], ah[0], ah[1], ah[2], ah[3], bh[h*2], bh[h*2+1]);
                    mma_bf16(accS[j], ah[0], ah[1], ah[2], ah[3], bl[h*2], bl[h*2+1]);
                    mma_bf16(accS[j], al[0], al[1], al[2], al[3], bh[h*2], bh[h*2+1]);
                }
            }
        }

        // ---- epilogue: exp, mask, sums, STS u into swizzled staging tile
        #pragma unroll
        for (int j = 0; j < 8; j++) {
            float e0 = exp2f(accS[j][0] * CE);
            float e1 = exp2f(accS[j][1] * CE);
            float e2 = exp2f(accS[j][2] * CE);
            float e3 = exp2f(accS[j][3] * CE);
            rsa0 += e0 + e1;
            rsa1 += e2 + e3;
            float a0 = mk0[j].x ? 0.f : e0;
            float a1 = mk0[j].y ? 0.f : e1;
            float a2 = mk1[j].x ? 0.f : e2;
            float a3 = mk1[j].y ? 0.f : e3;
            rsu0 += a0 + a1;
            rsu1 += a2 + a3;
            *(__half2*)(usr0 + ((j ^ swr0) * 16)) = __floats2half2_rn(a0, a1);
            *(__half2*)(usr1 + ((j ^ swr1) * 16)) = __floats2half2_rn(a2, a3);
        }
        __syncthreads();   // staging tile complete

        // ---- coalesced STG.128 of the 8KB swizzled tile
        {
            uint4* gU = gUrow + (size_t)kt * 512;
            const uint4* sU = (const uint4*)(smem + US);
            #pragma unroll
            for (int it = 0; it < 4; it++)
                gU[tid + it * 128] = sU[tid + it * 128];
        }
    }

    // ---- denominators: butterfly over tig lanes
    #pragma unroll
    for (int o = 1; o <= 2; o <<= 1) {
        rsa0 += __shfl_xor_sync(0xffffffffu, rsa0, o);
        rsa1 += __shfl_xor_sync(0xffffffffu, rsa1, o);
        rsu0 += __shfl_xor_sync(0xffffffffu, rsu0, o);
        rsu1 += __shfl_xor_sync(0xffffffffu, rsu1, o);
    }
    if (tig == 0) {
        g_I[b * L_ + m0 + r0] = 1.f / (rsu0 + 1e-8f * rsa0);
        g_I[b * L_ + m0 + r1] = 1.f / (rsu1 + 1e-8f * rsa1);
    }
}

// ---------------- K2: read tile-blocked u -> attn=u*I write + O = u@V (fp16 mma)
// grid (L/64, B), block 128. Dyn smem 49408B (4 CTAs/SM).
// layout: U[d] 0+d*8192, VH[d] 16384+d*8192, VL[d] 32768+d*8192, SI 49152
__global__ __launch_bounds__(128, 4) void av_kernel(float* __restrict__ attn,
                                                    float* __restrict__ out) {
    extern __shared__ char smem[];
    const int UB = 0, VH = 16384, VL = 32768, SI = 49152;
    int b = blockIdx.y, m0 = blockIdx.x * 64, tid = threadIdx.x;
    int warp = tid >> 5, lane = tid & 31, gid = lane >> 2, tig = lane & 3;
    uint32_t sm = smem_u32(smem);
    float* sI = (float*)(smem + SI);

    if (tid < 64) sI[tid] = g_I[b * L_ + m0 + tid];

    const uint4* gUrow = (const uint4*)(g_u + (((size_t)b * 32 + (m0 >> 6)) * 32) * 4096);

    // prologue: U(0) linear copy, V(0)
    {
        #pragma unroll
        for (int it = 0; it < 4; it++)
            cp16(sm + UB + (tid + it * 128) * 16, gUrow + tid + it * 128);
        #pragma unroll
        for (int it = 0; it < 4; it++) {
            int i = tid + it * 128, r = i >> 3, c = i & 7;
            uint32_t o = r * 128 + ((c ^ (r & 7)) * 16);
            cp16(sm + VH + o, g_VhT + ((size_t)b * D_ + r) * L_ + c * 8);
            cp16(sm + VL + o, g_VlT + ((size_t)b * D_ + r) * L_ + c * 8);
        }
        cp_commit();
    }

    uint32_t sw = lane & 7;
    uint32_t cA = lane >> 4;
    uint32_t cB = (lane >> 3) & 1;
    int rA = warp * 16 + (lane & 15);
    uint32_t rowBoff[4];
    #pragma unroll
    for (int g = 0; g < 4; g++)
        rowBoff[g] = (uint32_t)((g * 16 + ((lane >> 4) & 1) * 8 + (lane & 7)) * 128);

    int r0 = warp * 16 + gid, r1 = r0 + 8;

    float accO[8][4];
    #pragma unroll
    for (int j = 0; j < 8; j++)
        #pragma unroll
        for (int x = 0; x < 4; x++) accO[j][x] = 0.f;

    float I0 = 0.f, I1 = 0.f;

    for (int kt = 0; kt < 32; kt++) {
        int d = kt & 1, n0 = kt * 64;
        cp_wait0();
        __syncthreads();
        if (kt == 0) { I0 = sI[r0]; I1 = sI[r1]; }

        if (kt < 31) {              // prefetch U,V(kt+1)
            int d2 = (kt + 1) & 1, n2 = (kt + 1) * 64;
            const uint4* ub = gUrow + (size_t)(kt + 1) * 512;
            #pragma unroll
            for (int it = 0; it < 4; it++)
                cp16(sm + UB + d2 * 8192 + (tid + it * 128) * 16, ub + tid + it * 128);
            #pragma unroll
            for (int it = 0; it < 4; it++) {
                int i = tid + it * 128, r = i >> 3, c = i & 7;
                uint32_t o = r * 128 + ((c ^ (r & 7)) * 16);
                cp16(sm + VH + d2 * 8192 + o, g_VhT + ((size_t)b * D_ + r) * L_ + n2 + c * 8);
                cp16(sm + VL + d2 * 8192 + o, g_VlT + ((size_t)b * D_ + r) * L_ + n2 + c * 8);
            }
            cp_commit();
        }

        uint32_t aU = sm + UB + d * 8192 + rA * 128;
        uint32_t vh_base = sm + VH + d * 8192, vl_base = sm + VL + d * 8192;

        #pragma unroll
        for (int kk = 0; kk < 4; kk++) {
            uint32_t oA = ((cA + 2*kk) ^ sw) * 16;
            uint32_t oB = ((cB + 2*kk) ^ sw) * 16;
            uint32_t ua[4];
            ldsm_x4(ua[0], ua[1], ua[2], ua[3], aU + oA);

            // attn write: fragments -> float2 * I
            {
                int c = kk * 16 + tig * 2;
                float2 f0 = __half22float2(*(__half2*)&ua[0]);   // (r0, c)
                float2 f1 = __half22float2(*(__half2*)&ua[1]);   // (r1, c)
                float2 f2 = __half22float2(*(__half2*)&ua[2]);   // (r0, c+8)
                float2 f3 = __half22float2(*(__half2*)&ua[3]);   // (r1, c+8)
                size_t ro0 = ((size_t)b * L_ + m0 + r0) * L_ + n0;
                size_t ro1 = ((size_t)b * L_ + m0 + r1) * L_ + n0;
                *(float2*)(attn + ro0 + c)     = make_float2(f0.x * I0, f0.y * I0);
                *(float2*)(attn + ro1 + c)     = make_float2(f1.x * I1, f1.y * I1);
                *(float2*)(attn + ro0 + c + 8) = make_float2(f2.x * I0, f2.y * I0);
                *(float2*)(attn + ro1 + c + 8) = make_float2(f3.x * I1, f3.y * I1);
            }

            #pragma unroll
            for (int g = 0; g < 4; g++) {
                uint32_t vh[4], vl[4];
                ldsm_x4(vh[0], vh[1], vh[2], vh[3], vh_base + rowBoff[g] + oB);
                ldsm_x4(vl[0], vl[1], vl[2], vl[3], vl_base + rowBoff[g] + oB);
                #pragma unroll
                for (int h = 0; h < 2; h++) {
                    int j = g*2 + h;
                    mma_f16(accO[j], ua[0], ua[1], ua[2], ua[3], vh[h*2], vh[h*2+1]);
                    mma_f16(accO[j], ua[0], ua[1], ua[2], ua[3], vl[h*2], vl[h*2+1]);
                }
            }
        }
    }

    // ---- out epilogue: O = O_u * I
    #pragma unroll
    for (int j = 0; j < 8; j++) {
        int c = j*8 + tig*2;
        *(float2*)(out + ((size_t)b * L_ + m0 + r0) * D_ + c) =
            make_float2(accO[j][0] * I0, accO[j][1] * I0);
        *(float2*)(out + ((size_t)b * L_ + m0 + r1) * D_ + c) =
            make_float2(accO[j][2] * I1, accO[j][3] * I1);
    }
}

// ----------------------------------------------------------------- launcher
extern "C" void kernel_launch(void* const* d_in, const int* in_sizes, int n_in,
                              void* d_out, int out_size) {
    const float* q = (const float*)d_in[0];
    const float* k = (const float*)d_in[1];
    const float* v = (const float*)d_in[2];
    const int* mask = (const int*)d_in[3];
    float* out  = (float*)d_out;
    float* attn = out + (size_t)B_ * L_ * D_;

    cudaFuncSetAttribute(scores_kernel, cudaFuncAttributeMaxDynamicSharedMemorySize, 57344);
    cudaFuncSetAttribute(av_kernel,     cudaFuncAttributeMaxDynamicSharedMemorySize, 49408);

    int n = NE, nb = (n + 255) / 256;
    split_kernel<<<nb, 256>>>(q, 0, n);
    split_kernel<<<nb, 256>>>(k, 1, n);
    vtrans_kernel<<<dim3(L_/32, 2, B_), dim3(32, 8)>>>(v);

    scores_kernel<<<dim3(L_/64, B_), 128, 57344>>>(mask);
    av_kernel<<<dim3(L_/64, B_), 128, 49408>>>(attn, out);
}

// round 12
// speedup vs baseline: 1.7084x; 1.1164x over previous
#include <cuda_runtime.h>
#include <cuda_fp16.h>
#include <cstdint>

#define B_ 16
#define L_ 2048
#define D_ 64
#define NE (B_*L_*D_)
#define CE 0.18033688011112042f     // (1/8)*log2(e)

// device scratch (no allocation)
__device__ __half g_Qf[NE], g_Kf[NE];                 // fp16 Q, K [b][row][d]
__device__ __half g_VT[NE];                           // fp16 V transposed [b][d][k]
__device__ __half g_u[(size_t)B_*L_*L_];              // u, tile-blocked swizzled 8KB tiles
__device__ float g_I[B_*L_];                          // per-row 1/denom

// ---------------------------------------------------------------- helpers
__device__ __forceinline__ uint32_t smem_u32(const void* p) {
    return (uint32_t)__cvta_generic_to_shared(p);
}
__device__ __forceinline__ void cp16(uint32_t dst, const void* src) {
    asm volatile("cp.async.cg.shared.global [%0], [%1], 16;" :: "r"(dst), "l"(src));
}
__device__ __forceinline__ void cp_commit() { asm volatile("cp.async.commit_group;"); }
__device__ __forceinline__ void cp_wait0()  { asm volatile("cp.async.wait_group 0;"); }

__device__ __forceinline__ void ldsm_x4(uint32_t& r0, uint32_t& r1, uint32_t& r2, uint32_t& r3,
                                        uint32_t addr) {
    asm volatile("ldmatrix.sync.aligned.m8n8.x4.shared.b16 {%0,%1,%2,%3}, [%4];"
                 : "=r"(r0), "=r"(r1), "=r"(r2), "=r"(r3) : "r"(addr));
}
__device__ __forceinline__ void mma_f16(float* c,
                                        uint32_t a0, uint32_t a1, uint32_t a2, uint32_t a3,
                                        uint32_t b0, uint32_t b1) {
    asm volatile(
        "mma.sync.aligned.m16n8k16.row.col.f32.f16.f16.f32 "
        "{%0,%1,%2,%3}, {%4,%5,%6,%7}, {%8,%9}, {%0,%1,%2,%3};\n"
        : "+f"(c[0]), "+f"(c[1]), "+f"(c[2]), "+f"(c[3])
        : "r"(a0), "r"(a1), "r"(a2), "r"(a3), "r"(b0), "r"(b1));
}

// ---------------------------------------------------------------- K0a: Q/K -> fp16
__global__ __launch_bounds__(256) void prep_qk(const float* __restrict__ q,
                                               const float* __restrict__ k, int n) {
    int i = (blockIdx.x * blockDim.x + threadIdx.x) * 2;
    const float* src = blockIdx.y ? k : q;
    __half* dst = blockIdx.y ? g_Kf : g_Qf;
    if (i < n) {
        float2 x = *(const float2*)(src + i);
        *(__half2*)(dst + i) = __floats2half2_rn(x.x, x.y);
    }
}

// ---------------------------------------------------------------- K0b: V transpose -> [b][d][k] fp16
__global__ __launch_bounds__(256) void vtrans_kernel(const float* __restrict__ v) {
    __shared__ float t[32][33];
    int b = blockIdx.z, d0 = blockIdx.y * 32, k0 = blockIdx.x * 32;
    int tx = threadIdx.x, ty = threadIdx.y;   // block (32,8)
    #pragma unroll
    for (int j = 0; j < 32; j += 8)
        t[ty + j][tx] = v[((size_t)b * L_ + k0 + ty + j) * D_ + d0 + tx];
    __syncthreads();
    #pragma unroll
    for (int j = 0; j < 32; j += 8) {
        int d = d0 + ty + j;
        g_VT[((size_t)b * D_ + d) * L_ + k0 + tx] = __float2half_rn(t[tx][ty + j]);
    }
}

// ---------------- K1: fp16 scores GEMM + exp + mask + row sums; u staged + STG.128
// grid (L/64, B), block 128 (4 warps x 16 rows). Dyn smem 32768B (5 CTAs/SM).
// layout: QF 0 (8KB, 64r x 128B), K[d] 8192+d*8192 (8KB each), US 24576 (8KB)
__global__ __launch_bounds__(128, 5) void scores_kernel(const int* __restrict__ mask) {
    extern __shared__ char smem[];
    const int QF = 0, KB0 = 8192, US = 24576;
    int b = blockIdx.y, m0 = blockIdx.x * 64, tid = threadIdx.x;
    int warp = tid >> 5, lane = tid & 31, gid = lane >> 2, tig = lane & 3;
    uint32_t sm = smem_u32(smem);

    // prologue: Q + K0
    {
        const __half* qsrc = g_Qf + ((size_t)b * L_ + m0) * D_;
        const __half* ksrc = g_Kf + ((size_t)b * L_) * D_;
        #pragma unroll
        for (int it = 0; it < 4; it++) {
            int i = tid + it * 128, r = i >> 3, c = i & 7;
            uint32_t o = r * 128 + ((c ^ (r & 7)) * 16);
            cp16(sm + QF + o, qsrc + r * 64 + c * 8);
            cp16(sm + KB0 + o, ksrc + r * 64 + c * 8);
        }
        cp_commit();
    }

    uint32_t sw = lane & 7;
    uint32_t cA = lane >> 4;            // 0/1
    uint32_t cB = (lane >> 3) & 1;      // 0/1
    int rA = warp * 16 + (lane & 15);
    uint32_t aQ = sm + QF + rA * 128;
    uint32_t rowBoff[4];
    #pragma unroll
    for (int g = 0; g < 4; g++)
        rowBoff[g] = (uint32_t)((g * 16 + ((lane >> 4) & 1) * 8 + (lane & 7)) * 128);

    int r0 = warp * 16 + gid, r1 = r0 + 8;
    const int* mrow0 = mask + ((size_t)(b * L_ + m0 + r0)) * L_ + tig * 2;
    const int* mrow1 = mask + ((size_t)(b * L_ + m0 + r1)) * L_ + tig * 2;

    // u staging addresses (swizzled within the 8KB tile)
    char* usr0 = smem + US + r0 * 128 + tig * 4;
    char* usr1 = smem + US + r1 * 128 + tig * 4;
    int swr0 = r0 & 7, swr1 = r1 & 7;
    uint4* gUrow = (uint4*)(g_u + (((size_t)b * 32 + (m0 >> 6)) * 32) * 4096);

    float rsa0 = 0.f, rsa1 = 0.f, rsu0 = 0.f, rsu1 = 0.f;

    for (int kt = 0; kt < 32; kt++) {
        int d = kt & 1, n0 = kt * 64;
        cp_wait0();
        __syncthreads();

        // mask prefetch into registers (latency covered by scores GEMM)
        int2 mk0[8], mk1[8];
        #pragma unroll
        for (int j = 0; j < 8; j++) {
            mk0[j] = __ldg((const int2*)(mrow0 + n0 + j*8));
            mk1[j] = __ldg((const int2*)(mrow1 + n0 + j*8));
        }

        if (kt < 31) {              // prefetch K(kt+1)
            int d2 = (kt + 1) & 1, n2 = (kt + 1) * 64;
            const __half* ksrc = g_Kf + ((size_t)b * L_ + n2) * D_;
            #pragma unroll
            for (int it = 0; it < 4; it++) {
                int i = tid + it * 128, r = i >> 3, c = i & 7;
                uint32_t o = r * 128 + ((c ^ (r & 7)) * 16);
                cp16(sm + KB0 + d2 * 8192 + o, ksrc + r * 64 + c * 8);
            }
            cp_commit();
        }

        // ---- scores: S(16x64) = Q_warp(16x64) · K^T(64x64), single fp16 GEMM
        float accS[8][4];
        #pragma unroll
        for (int j = 0; j < 8; j++)
            #pragma unroll
            for (int x = 0; x < 4; x++) accS[j][x] = 0.f;

        uint32_t kb_base = sm + KB0 + d * 8192;
        #pragma unroll
        for (int kk = 0; kk < 4; kk++) {
            uint32_t oA = ((cA + 2*kk) ^ sw) * 16;
            uint32_t oB = ((cB + 2*kk) ^ sw) * 16;
            uint32_t a[4];
            ldsm_x4(a[0], a[1], a[2], a[3], aQ + oA);
            #pragma unroll
            for (int g = 0; g < 4; g++) {
                uint32_t bfr[4];
                ldsm_x4(bfr[0], bfr[1], bfr[2], bfr[3], kb_base + rowBoff[g] + oB);
                mma_f16(accS[g*2],   a[0], a[1], a[2], a[3], bfr[0], bfr[1]);
                mma_f16(accS[g*2+1], a[0], a[1], a[2], a[3], bfr[2], bfr[3]);
            }
        }

        // ---- epilogue: exp, mask, sums, STS u into swizzled staging tile
        #pragma unroll
        for (int j = 0; j < 8; j++) {
            float e0 = exp2f(accS[j][0] * CE);
            float e1 = exp2f(accS[j][1] * CE);
            float e2 = exp2f(accS[j][2] * CE);
            float e3 = exp2f(accS[j][3] * CE);
            rsa0 += e0 + e1;
            rsa1 += e2 + e3;
            float a0 = mk0[j].x ? 0.f : e0;
            float a1 = mk0[j].y ? 0.f : e1;
            float a2 = mk1[j].x ? 0.f : e2;
            float a3 = mk1[j].y ? 0.f : e3;
            rsu0 += a0 + a1;
            rsu1 += a2 + a3;
            *(__half2*)(usr0 + ((j ^ swr0) * 16)) = __floats2half2_rn(a0, a1);
            *(__half2*)(usr1 + ((j ^ swr1) * 16)) = __floats2half2_rn(a2, a3);
        }
        __syncthreads();   // staging tile complete

        // ---- coalesced STG.128 of the 8KB swizzled tile
        {
            uint4* gU = gUrow + (size_t)kt * 512;
            const uint4* sU = (const uint4*)(smem + US);
            #pragma unroll
            for (int it = 0; it < 4; it++)
                gU[tid + it * 128] = sU[tid + it * 128];
        }
    }

    // ---- denominators: butterfly over tig lanes
    #pragma unroll
    for (int o = 1; o <= 2; o <<= 1) {
        rsa0 += __shfl_xor_sync(0xffffffffu, rsa0, o);
        rsa1 += __shfl_xor_sync(0xffffffffu, rsa1, o);
        rsu0 += __shfl_xor_sync(0xffffffffu, rsu0, o);
        rsu1 += __shfl_xor_sync(0xffffffffu, rsu1, o);
    }
    if (tig == 0) {
        g_I[b * L_ + m0 + r0] = 1.f / (rsu0 + 1e-8f * rsa0);
        g_I[b * L_ + m0 + r1] = 1.f / (rsu1 + 1e-8f * rsa1);
    }
}

// ---------------- K2: read tile-blocked u -> attn=u*I write + O = u@V (fp16 mma)
// grid (L/64, B), block 128. Dyn smem 33024B (6 CTAs/SM).
// layout: U[d] 0+d*8192, V[d] 16384+d*8192, SI 32768
__global__ __launch_bounds__(128, 6) void av_kernel(float* __restrict__ attn,
                                                    float* __restrict__ out) {
    extern __shared__ char smem[];
    const int UB = 0, VB = 16384, SI = 32768;
    int b = blockIdx.y, m0 = blockIdx.x * 64, tid = threadIdx.x;
    int warp = tid >> 5, lane = tid & 31, gid = lane >> 2, tig = lane & 3;
    uint32_t sm = smem_u32(smem);
    float* sI = (float*)(smem + SI);

    if (tid < 64) sI[tid] = g_I[b * L_ + m0 + tid];

    const uint4* gUrow = (const uint4*)(g_u + (((size_t)b * 32 + (m0 >> 6)) * 32) * 4096);

    // prologue: U(0) linear copy, V(0)
    {
        #pragma unroll
        for (int it = 0; it < 4; it++)
            cp16(sm + UB + (tid + it * 128) * 16, gUrow + tid + it * 128);
        #pragma unroll
        for (int it = 0; it < 4; it++) {
            int i = tid + it * 128, r = i >> 3, c = i & 7;
            uint32_t o = r * 128 + ((c ^ (r & 7)) * 16);
            cp16(sm + VB + o, g_VT + ((size_t)b * D_ + r) * L_ + c * 8);
        }
        cp_commit();
    }

    uint32_t sw = lane & 7;
    uint32_t cA = lane >> 4;
    uint32_t cB = (lane >> 3) & 1;
    int rA = warp * 16 + (lane & 15);
    uint32_t rowBoff[4];
    #pragma unroll
    for (int g = 0; g < 4; g++)
        rowBoff[g] = (uint32_t)((g * 16 + ((lane >> 4) & 1) * 8 + (lane & 7)) * 128);

    int r0 = warp * 16 + gid, r1 = r0 + 8;

    float accO[8][4];
    #pragma unroll
    for (int j = 0; j < 8; j++)
        #pragma unroll
        for (int x = 0; x < 4; x++) accO[j][x] = 0.f;

    float I0 = 0.f, I1 = 0.f;

    for (int kt = 0; kt < 32; kt++) {
        int d = kt & 1, n0 = kt * 64;
        cp_wait0();
        __syncthreads();
        if (kt == 0) { I0 = sI[r0]; I1 = sI[r1]; }

        if (kt < 31) {              // prefetch U,V(kt+1)
            int d2 = (kt + 1) & 1, n2 = (kt + 1) * 64;
            const uint4* ub = gUrow + (size_t)(kt + 1) * 512;
            #pragma unroll
            for (int it = 0; it < 4; it++)
                cp16(sm + UB + d2 * 8192 + (tid + it * 128) * 16, ub + tid + it * 128);
            #pragma unroll
            for (int it = 0; it < 4; it++) {
                int i = tid + it * 128, r = i >> 3, c = i & 7;
                uint32_t o = r * 128 + ((c ^ (r & 7)) * 16);
                cp16(sm + VB + d2 * 8192 + o, g_VT + ((size_t)b * D_ + r) * L_ + n2 + c * 8);
            }
            cp_commit();
        }

        uint32_t aU = sm + UB + d * 8192 + rA * 128;
        uint32_t vb_base = sm + VB + d * 8192;

        #pragma unroll
        for (int kk = 0; kk < 4; kk++) {
            uint32_t oA = ((cA + 2*kk) ^ sw) * 16;
            uint32_t oB = ((cB + 2*kk) ^ sw) * 16;
            uint32_t ua[4];
            ldsm_x4(ua[0], ua[1], ua[2], ua[3], aU + oA);

            // attn write: fragments -> float2 * I
            {
                int c = kk * 16 + tig * 2;
                float2 f0 = __half22float2(*(__half2*)&ua[0]);   // (r0, c)
                float2 f1 = __half22float2(*(__half2*)&ua[1]);   // (r1, c)
                float2 f2 = __half22float2(*(__half2*)&ua[2]);   // (r0, c+8)
                float2 f3 = __half22float2(*(__half2*)&ua[3]);   // (r1, c+8)
                size_t ro0 = ((size_t)b * L_ + m0 + r0) * L_ + n0;
                size_t ro1 = ((size_t)b * L_ + m0 + r1) * L_ + n0;
                *(float2*)(attn + ro0 + c)     = make_float2(f0.x * I0, f0.y * I0);
                *(float2*)(attn + ro1 + c)     = make_float2(f1.x * I1, f1.y * I1);
                *(float2*)(attn + ro0 + c + 8) = make_float2(f2.x * I0, f2.y * I0);
                *(float2*)(attn + ro1 + c + 8) = make_float2(f3.x * I1, f3.y * I1);
            }

            #pragma unroll
            for (int g = 0; g < 4; g++) {
                uint32_t vf[4];
                ldsm_x4(vf[0], vf[1], vf[2], vf[3], vb_base + rowBoff[g] + oB);
                mma_f16(accO[g*2],   ua[0], ua[1], ua[2], ua[3], vf[0], vf[1]);
                mma_f16(accO[g*2+1], ua[0], ua[1], ua[2], ua[3], vf[2], vf[3]);
            }
        }
    }

    // ---- out epilogue: O = O_u * I
    #pragma unroll
    for (int j = 0; j < 8; j++) {
        int c = j*8 + tig*2;
        *(float2*)(out + ((size_t)b * L_ + m0 + r0) * D_ + c) =
            make_float2(accO[j][0] * I0, accO[j][1] * I0);
        *(float2*)(out + ((size_t)b * L_ + m0 + r1) * D_ + c) =
            make_float2(accO[j][2] * I1, accO[j][3] * I1);
    }
}

// ----------------------------------------------------------------- launcher
extern "C" void kernel_launch(void* const* d_in, const int* in_sizes, int n_in,
                              void* d_out, int out_size) {
    const float* q = (const float*)d_in[0];
    const float* k = (const float*)d_in[1];
    const float* v = (const float*)d_in[2];
    const int* mask = (const int*)d_in[3];
    float* out  = (float*)d_out;
    float* attn = out + (size_t)B_ * L_ * D_;

    cudaFuncSetAttribute(scores_kernel, cudaFuncAttributeMaxDynamicSharedMemorySize, 32768);
    cudaFuncSetAttribute(av_kernel,     cudaFuncAttributeMaxDynamicSharedMemorySize, 33024);

    int n = NE;
    prep_qk<<<dim3((n/2 + 255) / 256, 2), 256>>>(q, k, n);
    vtrans_kernel<<<dim3(L_/32, 2, B_), dim3(32, 8)>>>(v);

    scores_kernel<<<dim3(L_/64, B_), 128, 32768>>>(mask);
    av_kernel<<<dim3(L_/64, B_), 128, 33024>>>(attn, out);
}

// round 13
// speedup vs baseline: 1.7284x; 1.0117x over previous
#include <cuda_runtime.h>
#include <cuda_fp16.h>
#include <cstdint>

#define B_ 16
#define L_ 2048
#define D_ 64
#define NE (B_*L_*D_)
#define CE 0.18033688011112042f     // (1/8)*log2(e)

// device scratch (no allocation)
__device__ __half g_Qf[NE], g_Kf[NE];                 // fp16 Q, K [b][row][d]
__device__ __half g_VT[NE];                           // fp16 V transposed [b][d][k]
__device__ __half g_u[(size_t)B_*L_*L_];              // u, tile-blocked swizzled 8KB tiles
__device__ float2 g_Psum[2*B_*L_];                    // per-z partial (sum_all, sum_unmasked)
__device__ float g_I[B_*L_];                          // per-row 1/denom

// ---------------------------------------------------------------- helpers
__device__ __forceinline__ uint32_t smem_u32(const void* p) {
    return (uint32_t)__cvta_generic_to_shared(p);
}
__device__ __forceinline__ void cp16(uint32_t dst, const void* src) {
    asm volatile("cp.async.cg.shared.global [%0], [%1], 16;" :: "r"(dst), "l"(src));
}
__device__ __forceinline__ void cp_commit() { asm volatile("cp.async.commit_group;"); }
__device__ __forceinline__ void cp_wait0()  { asm volatile("cp.async.wait_group 0;"); }

__device__ __forceinline__ void ldsm_x4(uint32_t& r0, uint32_t& r1, uint32_t& r2, uint32_t& r3,
                                        uint32_t addr) {
    asm volatile("ldmatrix.sync.aligned.m8n8.x4.shared.b16 {%0,%1,%2,%3}, [%4];"
                 : "=r"(r0), "=r"(r1), "=r"(r2), "=r"(r3) : "r"(addr));
}
__device__ __forceinline__ void mma_f16(float* c,
                                        uint32_t a0, uint32_t a1, uint32_t a2, uint32_t a3,
                                        uint32_t b0, uint32_t b1) {
    asm volatile(
        "mma.sync.aligned.m16n8k16.row.col.f32.f16.f16.f32 "
        "{%0,%1,%2,%3}, {%4,%5,%6,%7}, {%8,%9}, {%0,%1,%2,%3};\n"
        : "+f"(c[0]), "+f"(c[1]), "+f"(c[2]), "+f"(c[3])
        : "r"(a0), "r"(a1), "r"(a2), "r"(a3), "r"(b0), "r"(b1));
}

// ---------------------------------------------------------------- K0a: Q/K -> fp16
__global__ __launch_bounds__(256) void prep_qk(const float* __restrict__ q,
                                               const float* __restrict__ k, int n) {
    int i = (blockIdx.x * blockDim.x + threadIdx.x) * 2;
    const float* src = blockIdx.y ? k : q;
    __half* dst = blockIdx.y ? g_Kf : g_Qf;
    if (i < n) {
        float2 x = *(const float2*)(src + i);
        *(__half2*)(dst + i) = __floats2half2_rn(x.x, x.y);
    }
}

// ---------------------------------------------------------------- K0b: V transpose -> [b][d][k] fp16
__global__ __launch_bounds__(256) void vtrans_kernel(const float* __restrict__ v) {
    __shared__ float t[32][33];
    int b = blockIdx.z, d0 = blockIdx.y * 32, k0 = blockIdx.x * 32;
    int tx = threadIdx.x, ty = threadIdx.y;   // block (32,8)
    #pragma unroll
    for (int j = 0; j < 32; j += 8)
        t[ty + j][tx] = v[((size_t)b * L_ + k0 + ty + j) * D_ + d0 + tx];
    __syncthreads();
    #pragma unroll
    for (int j = 0; j < 32; j += 8) {
        int d = d0 + ty + j;
        g_VT[((size_t)b * D_ + d) * L_ + k0 + tx] = __float2half_rn(t[tx][ty + j]);
    }
}

// ---------------- K1: fp16 scores GEMM + exp + mask + partial row sums (split-K z=2)
// grid (L/64, B, 2), block 128 (4 warps x 16 rows). Dyn smem 32768B.
// Each z handles 16 k-tiles. layout: QF 0, K[d] 8192+d*8192, US 24576
__global__ __launch_bounds__(128, 5) void scores_kernel(const int* __restrict__ mask) {
    extern __shared__ char smem[];
    const int QF = 0, KB0 = 8192, US = 24576;
    int b = blockIdx.y, m0 = blockIdx.x * 64, z = blockIdx.z, tid = threadIdx.x;
    int warp = tid >> 5, lane = tid & 31, gid = lane >> 2, tig = lane & 3;
    uint32_t sm = smem_u32(smem);
    int kt0 = z * 16;

    // prologue: Q + K(kt0)
    {
        const __half* qsrc = g_Qf + ((size_t)b * L_ + m0) * D_;
        const __half* ksrc = g_Kf + ((size_t)b * L_ + kt0 * 64) * D_;
        #pragma unroll
        for (int it = 0; it < 4; it++) {
            int i = tid + it * 128, r = i >> 3, c = i & 7;
            uint32_t o = r * 128 + ((c ^ (r & 7)) * 16);
            cp16(sm + QF + o, qsrc + r * 64 + c * 8);
            cp16(sm + KB0 + o, ksrc + r * 64 + c * 8);
        }
        cp_commit();
    }

    uint32_t sw = lane & 7;
    uint32_t cA = lane >> 4;            // 0/1
    uint32_t cB = (lane >> 3) & 1;      // 0/1
    int rA = warp * 16 + (lane & 15);
    uint32_t aQ = sm + QF + rA * 128;
    uint32_t rowBoff[4];
    #pragma unroll
    for (int g = 0; g < 4; g++)
        rowBoff[g] = (uint32_t)((g * 16 + ((lane >> 4) & 1) * 8 + (lane & 7)) * 128);

    int r0 = warp * 16 + gid, r1 = r0 + 8;
    const int* mrow0 = mask + ((size_t)(b * L_ + m0 + r0)) * L_ + tig * 2;
    const int* mrow1 = mask + ((size_t)(b * L_ + m0 + r1)) * L_ + tig * 2;

    // u staging addresses (swizzled within the 8KB tile)
    char* usr0 = smem + US + r0 * 128 + tig * 4;
    char* usr1 = smem + US + r1 * 128 + tig * 4;
    int swr0 = r0 & 7, swr1 = r1 & 7;
    uint4* gUrow = (uint4*)(g_u + (((size_t)b * 32 + (m0 >> 6)) * 32) * 4096);

    float rsa0 = 0.f, rsa1 = 0.f, rsu0 = 0.f, rsu1 = 0.f;

    for (int t = 0; t < 16; t++) {
        int kt = kt0 + t;
        int d = t & 1, n0 = kt * 64;
        cp_wait0();
        __syncthreads();

        // mask prefetch into registers (latency covered by scores GEMM)
        int2 mk0[8], mk1[8];
        #pragma unroll
        for (int j = 0; j < 8; j++) {
            mk0[j] = __ldg((const int2*)(mrow0 + n0 + j*8));
            mk1[j] = __ldg((const int2*)(mrow1 + n0 + j*8));
        }

        if (t < 15) {               // prefetch K(kt+1)
            int d2 = (t + 1) & 1, n2 = (kt + 1) * 64;
            const __half* ksrc = g_Kf + ((size_t)b * L_ + n2) * D_;
            #pragma unroll
            for (int it = 0; it < 4; it++) {
                int i = tid + it * 128, r = i >> 3, c = i & 7;
                uint32_t o = r * 128 + ((c ^ (r & 7)) * 16);
                cp16(sm + KB0 + d2 * 8192 + o, ksrc + r * 64 + c * 8);
            }
            cp_commit();
        }

        // ---- scores: S(16x64) = Q_warp(16x64) · K^T(64x64), single fp16 GEMM
        float accS[8][4];
        #pragma unroll
        for (int j = 0; j < 8; j++)
            #pragma unroll
            for (int x = 0; x < 4; x++) accS[j][x] = 0.f;

        uint32_t kb_base = sm + KB0 + d * 8192;
        #pragma unroll
        for (int kk = 0; kk < 4; kk++) {
            uint32_t oA = ((cA + 2*kk) ^ sw) * 16;
            uint32_t oB = ((cB + 2*kk) ^ sw) * 16;
            uint32_t a[4];
            ldsm_x4(a[0], a[1], a[2], a[3], aQ + oA);
            #pragma unroll
            for (int g = 0; g < 4; g++) {
                uint32_t bfr[4];
                ldsm_x4(bfr[0], bfr[1], bfr[2], bfr[3], kb_base + rowBoff[g] + oB);
                mma_f16(accS[g*2],   a[0], a[1], a[2], a[3], bfr[0], bfr[1]);
                mma_f16(accS[g*2+1], a[0], a[1], a[2], a[3], bfr[2], bfr[3]);
            }
        }

        // ---- epilogue: exp, mask, sums, STS u into swizzled staging tile
        #pragma unroll
        for (int j = 0; j < 8; j++) {
            float e0 = exp2f(accS[j][0] * CE);
            float e1 = exp2f(accS[j][1] * CE);
            float e2 = exp2f(accS[j][2] * CE);
            float e3 = exp2f(accS[j][3] * CE);
            rsa0 += e0 + e1;
            rsa1 += e2 + e3;
            float a0 = mk0[j].x ? 0.f : e0;
            float a1 = mk0[j].y ? 0.f : e1;
            float a2 = mk1[j].x ? 0.f : e2;
            float a3 = mk1[j].y ? 0.f : e3;
            rsu0 += a0 + a1;
            rsu1 += a2 + a3;
            *(__half2*)(usr0 + ((j ^ swr0) * 16)) = __floats2half2_rn(a0, a1);
            *(__half2*)(usr1 + ((j ^ swr1) * 16)) = __floats2half2_rn(a2, a3);
        }
        __syncthreads();   // staging tile complete

        // ---- coalesced STG.128 of the 8KB swizzled tile
        {
            uint4* gU = gUrow + (size_t)kt * 512;
            const uint4* sU = (const uint4*)(smem + US);
            #pragma unroll
            for (int it = 0; it < 4; it++)
                gU[tid + it * 128] = sU[tid + it * 128];
        }
    }

    // ---- partial sums: butterfly over tig lanes, write per-z
    #pragma unroll
    for (int o = 1; o <= 2; o <<= 1) {
        rsa0 += __shfl_xor_sync(0xffffffffu, rsa0, o);
        rsa1 += __shfl_xor_sync(0xffffffffu, rsa1, o);
        rsu0 += __shfl_xor_sync(0xffffffffu, rsu0, o);
        rsu1 += __shfl_xor_sync(0xffffffffu, rsu1, o);
    }
    if (tig == 0) {
        g_Psum[z * (B_*L_) + b * L_ + m0 + r0] = make_float2(rsa0, rsu0);
        g_Psum[z * (B_*L_) + b * L_ + m0 + r1] = make_float2(rsa1, rsu1);
    }
}

// ---------------------------------------------------------------- K1b: combine partials -> g_I
__global__ __launch_bounds__(256) void combine_kernel() {
    int row = blockIdx.x * blockDim.x + threadIdx.x;
    float2 p0 = g_Psum[row];
    float2 p1 = g_Psum[B_*L_ + row];
    g_I[row] = 1.f / ((p0.y + p1.y) + 1e-8f * (p0.x + p1.x));
}

// ---------------- K2: read tile-blocked u -> attn=u*I write + O += u@V*I (split-K z=2)
// grid (L/64, B, 2), block 128. Dyn smem 33024B. atomicAdd into zeroed out.
// layout: U[d] 0+d*8192, V[d] 16384+d*8192, SI 32768
__global__ __launch_bounds__(128, 6) void av_kernel(float* __restrict__ attn,
                                                    float* __restrict__ out) {
    extern __shared__ char smem[];
    const int UB = 0, VB = 16384, SI = 32768;
    int b = blockIdx.y, m0 = blockIdx.x * 64, z = blockIdx.z, tid = threadIdx.x;
    int warp = tid >> 5, lane = tid & 31, gid = lane >> 2, tig = lane & 3;
    uint32_t sm = smem_u32(smem);
    float* sI = (float*)(smem + SI);
    int kt0 = z * 16;

    if (tid < 64) sI[tid] = g_I[b * L_ + m0 + tid];

    const uint4* gUrow = (const uint4*)(g_u + (((size_t)b * 32 + (m0 >> 6)) * 32) * 4096);

    // prologue: U(kt0) linear copy, V(kt0)
    {
        const uint4* ub = gUrow + (size_t)kt0 * 512;
        #pragma unroll
        for (int it = 0; it < 4; it++)
            cp16(sm + UB + (tid + it * 128) * 16, ub + tid + it * 128);
        #pragma unroll
        for (int it = 0; it < 4; it++) {
            int i = tid + it * 128, r = i >> 3, c = i & 7;
            uint32_t o = r * 128 + ((c ^ (r & 7)) * 16);
            cp16(sm + VB + o, g_VT + ((size_t)b * D_ + r) * L_ + kt0 * 64 + c * 8);
        }
        cp_commit();
    }

    uint32_t sw = lane & 7;
    uint32_t cA = lane >> 4;
    uint32_t cB = (lane >> 3) & 1;
    int rA = warp * 16 + (lane & 15);
    uint32_t rowBoff[4];
    #pragma unroll
    for (int g = 0; g < 4; g++)
        rowBoff[g] = (uint32_t)((g * 16 + ((lane >> 4) & 1) * 8 + (lane & 7)) * 128);

    int r0 = warp * 16 + gid, r1 = r0 + 8;

    float accO[8][4];
    #pragma unroll
    for (int j = 0; j < 8; j++)
        #pragma unroll
        for (int x = 0; x < 4; x++) accO[j][x] = 0.f;

    float I0 = 0.f, I1 = 0.f;

    for (int t = 0; t < 16; t++) {
        int kt = kt0 + t;
        int d = t & 1, n0 = kt * 64;
        cp_wait0();
        __syncthreads();
        if (t == 0) { I0 = sI[r0]; I1 = sI[r1]; }

        if (t < 15) {               // prefetch U,V(kt+1)
            int d2 = (t + 1) & 1, n2 = (kt + 1) * 64;
            const uint4* ub = gUrow + (size_t)(kt + 1) * 512;
            #pragma unroll
            for (int it = 0; it < 4; it++)
                cp16(sm + UB + d2 * 8192 + (tid + it * 128) * 16, ub + tid + it * 128);
            #pragma unroll
            for (int it = 0; it < 4; it++) {
                int i = tid + it * 128, r = i >> 3, c = i & 7;
                uint32_t o = r * 128 + ((c ^ (r & 7)) * 16);
                cp16(sm + VB + d2 * 8192 + o, g_VT + ((size_t)b * D_ + r) * L_ + n2 + c * 8);
            }
            cp_commit();
        }

        uint32_t aU = sm + UB + d * 8192 + rA * 128;
        uint32_t vb_base = sm + VB + d * 8192;

        #pragma unroll
        for (int kk = 0; kk < 4; kk++) {
            uint32_t oA = ((cA + 2*kk) ^ sw) * 16;
            uint32_t oB = ((cB + 2*kk) ^ sw) * 16;
            uint32_t ua[4];
            ldsm_x4(ua[0], ua[1], ua[2], ua[3], aU + oA);

            // attn write: fragments -> float2 * I
            {
                int c = kk * 16 + tig * 2;
                float2 f0 = __half22float2(*(__half2*)&ua[0]);   // (r0, c)
                float2 f1 = __half22float2(*(__half2*)&ua[1]);   // (r1, c)
                float2 f2 = __half22float2(*(__half2*)&ua[2]);   // (r0, c+8)
                float2 f3 = __half22float2(*(__half2*)&ua[3]);   // (r1, c+8)
                size_t ro0 = ((size_t)b * L_ + m0 + r0) * L_ + n0;
                size_t ro1 = ((size_t)b * L_ + m0 + r1) * L_ + n0;
                *(float2*)(attn + ro0 + c)     = make_float2(f0.x * I0, f0.y * I0);
                *(float2*)(attn + ro1 + c)     = make_float2(f1.x * I1, f1.y * I1);
                *(float2*)(attn + ro0 + c + 8) = make_float2(f2.x * I0, f2.y * I0);
                *(float2*)(attn + ro1 + c + 8) = make_float2(f3.x * I1, f3.y * I1);
            }

            #pragma unroll
            for (int g = 0; g < 4; g++) {
                uint32_t vf[4];
                ldsm_x4(vf[0], vf[1], vf[2], vf[3], vb_base + rowBoff[g] + oB);
                mma_f16(accO[g*2],   ua[0], ua[1], ua[2], ua[3], vf[0], vf[1]);
                mma_f16(accO[g*2+1], ua[0], ua[1], ua[2], ua[3], vf[2], vf[3]);
            }
        }
    }

    // ---- out epilogue: atomicAdd partial O * I (out pre-zeroed)
    #pragma unroll
    for (int j = 0; j < 8; j++) {
        int c = j*8 + tig*2;
        float* o0 = out + ((size_t)b * L_ + m0 + r0) * D_ + c;
        float* o1 = out + ((size_t)b * L_ + m0 + r1) * D_ + c;
        atomicAdd(o0,     accO[j][0] * I0);
        atomicAdd(o0 + 1, accO[j][1] * I0);
        atomicAdd(o1,     accO[j][2] * I1);
        atomicAdd(o1 + 1, accO[j][3] * I1);
    }
}

// ----------------------------------------------------------------- launcher
extern "C" void kernel_launch(void* const* d_in, const int* in_sizes, int n_in,
                              void* d_out, int out_size) {
    const float* q = (const float*)d_in[0];
    const float* k = (const float*)d_in[1];
    const float* v = (const float*)d_in[2];
    const int* mask = (const int*)d_in[3];
    float* out  = (float*)d_out;
    float* attn = out + (size_t)B_ * L_ * D_;

    cudaFuncSetAttribute(scores_kernel, cudaFuncAttributeMaxDynamicSharedMemorySize, 32768);
    cudaFuncSetAttribute(av_kernel,     cudaFuncAttributeMaxDynamicSharedMemorySize, 33024);

    int n = NE;
    prep_qk<<<dim3((n/2 + 255) / 256, 2), 256>>>(q, k, n);
    vtrans_kernel<<<dim3(L_/32, 2, B_), dim3(32, 8)>>>(v);
    cudaMemsetAsync(out, 0, (size_t)NE * sizeof(float));

    scores_kernel<<<dim3(L_/64, B_, 2), 128, 32768>>>(mask);
    combine_kernel<<<(B_*L_)/256, 256>>>();
    av_kernel<<<dim3(L_/64, B_, 2), 128, 33024>>>(attn, out);
}